// round 3
// baseline (speedup 1.0000x reference)
#include <cuda_runtime.h>
#include <math.h>

#define SEQ   1024
#define BATCH 2
#define HID   768
#define NHEAD 12
#define HDIM  64
#define FFD   3072
#define MTOT  (BATCH*SEQ)   // 2048
#define BHTOT (BATCH*NHEAD) // 24

// ---------------- scratch (device globals: no allocation allowed) ----------------
__device__ float g_x [MTOT*HID];
__device__ float g_q [MTOT*HID];
__device__ float g_k [MTOT*HID];
__device__ float g_v [MTOT*HID];
__device__ float g_ao[MTOT*HID];
__device__ float g_r1[MTOT*HID];
__device__ float g_y [MTOT*HID];
__device__ float g_ff[MTOT*FFD];

// ---------------- LayerNorm: one block per row of 768 ----------------
__global__ void ln_kernel(const float* __restrict__ in, const float* __restrict__ g,
                          const float* __restrict__ b, float* __restrict__ out) {
    int row = blockIdx.x;
    const float* x = in + (size_t)row * HID;
    int t = threadIdx.x;
    float v0 = x[t], v1 = x[t + 256], v2 = x[t + 512];
    float s  = v0 + v1 + v2;
    float sq = v0 * v0 + v1 * v1 + v2 * v2;
    __shared__ float sh[16];
    #pragma unroll
    for (int o = 16; o; o >>= 1) {
        s  += __shfl_xor_sync(0xffffffffu, s,  o);
        sq += __shfl_xor_sync(0xffffffffu, sq, o);
    }
    int w = t >> 5, l = t & 31;
    if (!l) { sh[w] = s; sh[w + 8] = sq; }
    __syncthreads();
    if (w == 0) {
        float a = (l < 8) ? sh[l] : 0.f;
        float c = (l < 8) ? sh[l + 8] : 0.f;
        #pragma unroll
        for (int o = 4; o; o >>= 1) {
            a += __shfl_xor_sync(0xffffffffu, a, o);
            c += __shfl_xor_sync(0xffffffffu, c, o);
        }
        if (!l) { sh[0] = a; sh[1] = c; }
    }
    __syncthreads();
    float mean = sh[0] * (1.f / HID);
    float var  = sh[1] * (1.f / HID) - mean * mean;
    float rs   = rsqrtf(var + 1e-5f);
    float* o = out + (size_t)row * HID;
    o[t]       = (v0 - mean) * rs * g[t]       + b[t];
    o[t + 256] = (v1 - mean) * rs * g[t + 256] + b[t + 256];
    o[t + 512] = (v2 - mean) * rs * g[t + 512] + b[t + 512];
}

// ---------------- sgemm: C = A[M,K] @ B[K,N] + bias (+res / gelu) ----------------
// BM=BN=128, BK=8, 256 threads, 8x8 microtile. M%128==0, N%128==0, K%8==0 required.
// mode: 0 = +bias, 1 = +bias+res, 2 = gelu(+bias)
__global__ void __launch_bounds__(256) sgemm_kernel(
    const float* __restrict__ A, const float* __restrict__ Bm,
    const float* __restrict__ bias, const float* __restrict__ res,
    float* __restrict__ C, int M, int N, int K, int mode)
{
    __shared__ float As[8][128];
    __shared__ float Bs[8][128];
    int tid = threadIdx.x;
    int bm = blockIdx.y * 128, bn = blockIdx.x * 128;
    int arow = tid >> 1, acol = (tid & 1) * 4;
    int brow = tid >> 5, bcol = (tid & 31) * 4;
    int tx = tid & 15, ty = tid >> 4;
    int ms = ty * 8, ns = tx * 8;

    float acc[8][8];
    #pragma unroll
    for (int i = 0; i < 8; i++)
        #pragma unroll
        for (int j = 0; j < 8; j++) acc[i][j] = 0.f;

    const float* Ap = A  + (size_t)(bm + arow) * K + acol;
    const float* Bp = Bm + (size_t)brow * N + bn + bcol;

    for (int k0 = 0; k0 < K; k0 += 8) {
        float4 av = *(const float4*)(Ap + k0);
        float4 bv = *(const float4*)(Bp + (size_t)k0 * N);
        __syncthreads();
        As[acol + 0][arow] = av.x;
        As[acol + 1][arow] = av.y;
        As[acol + 2][arow] = av.z;
        As[acol + 3][arow] = av.w;
        *(float4*)&Bs[brow][bcol] = bv;
        __syncthreads();
        #pragma unroll
        for (int kk = 0; kk < 8; kk++) {
            float af[8], bf[8];
            *(float4*)(af)     = *(const float4*)&As[kk][ms];
            *(float4*)(af + 4) = *(const float4*)&As[kk][ms + 4];
            *(float4*)(bf)     = *(const float4*)&Bs[kk][ns];
            *(float4*)(bf + 4) = *(const float4*)&Bs[kk][ns + 4];
            #pragma unroll
            for (int i = 0; i < 8; i++)
                #pragma unroll
                for (int j = 0; j < 8; j++)
                    acc[i][j] += af[i] * bf[j];
        }
    }

    #pragma unroll
    for (int i = 0; i < 8; i++) {
        size_t crow = (size_t)(bm + ms + i);
        #pragma unroll
        for (int j0 = 0; j0 < 8; j0 += 4) {
            float o[4];
            #pragma unroll
            for (int jj = 0; jj < 4; jj++) {
                int col = bn + ns + j0 + jj;
                float val = acc[i][j0 + jj] + bias[col];
                if (mode == 1)      val += res[crow * N + col];
                else if (mode == 2) val = 0.5f * val * (1.f + erff(val * 0.70710678118654752f));
                o[jj] = val;
            }
            *(float4*)(C + crow * N + bn + ns + j0) = *(float4*)o;
        }
    }
}

// ---------------- L1 distance -> raw scores: -lam/8 * sum_d |q-k| ----------------
// 64x64 tile per block, 256 threads, 4x4 microtile; smem stored d-major.
__global__ void __launch_bounds__(256) dist_kernel(
    const float* __restrict__ Q, const float* __restrict__ K,
    const float* __restrict__ lamp, float* __restrict__ attn)
{
    __shared__ float Qs[64][68];
    __shared__ float Ks[64][68];
    int bh = blockIdx.z;
    int b = bh / NHEAD, h = bh - b * NHEAD;
    const float* Qb = Q + (size_t)b * SEQ * HID + h * HDIM + (size_t)blockIdx.y * 64 * HID;
    const float* Kb = K + (size_t)b * SEQ * HID + h * HDIM + (size_t)blockIdx.x * 64 * HID;
    int tid = threadIdx.x;
    int row = tid >> 2, dg = (tid & 3) * 16;
    #pragma unroll
    for (int i = 0; i < 4; i++) {
        float4 qv = *(const float4*)(Qb + (size_t)row * HID + dg + i * 4);
        float4 kv = *(const float4*)(Kb + (size_t)row * HID + dg + i * 4);
        Qs[dg + i*4 + 0][row] = qv.x; Qs[dg + i*4 + 1][row] = qv.y;
        Qs[dg + i*4 + 2][row] = qv.z; Qs[dg + i*4 + 3][row] = qv.w;
        Ks[dg + i*4 + 0][row] = kv.x; Ks[dg + i*4 + 1][row] = kv.y;
        Ks[dg + i*4 + 2][row] = kv.z; Ks[dg + i*4 + 3][row] = kv.w;
    }
    __syncthreads();
    int tx = tid & 15, ty = tid >> 4;
    int qs = ty * 4, ks = tx * 4;
    float acc[4][4];
    #pragma unroll
    for (int i = 0; i < 4; i++)
        #pragma unroll
        for (int j = 0; j < 4; j++) acc[i][j] = 0.f;
    #pragma unroll 16
    for (int d = 0; d < HDIM; d++) {
        float4 qf = *(const float4*)&Qs[d][qs];
        float4 kf = *(const float4*)&Ks[d][ks];
        float qa[4] = {qf.x, qf.y, qf.z, qf.w};
        float ka[4] = {kf.x, kf.y, kf.z, kf.w};
        #pragma unroll
        for (int i = 0; i < 4; i++)
            #pragma unroll
            for (int j = 0; j < 4; j++)
                acc[i][j] += fabsf(qa[i] - ka[j]);
    }
    float c = -(*lamp) * 0.125f;  // scale = 1/sqrt(64)
    float* outp = attn + (size_t)bh * SEQ * SEQ
                + ((size_t)blockIdx.y * 64 + qs) * SEQ + blockIdx.x * 64 + ks;
    #pragma unroll
    for (int i = 0; i < 4; i++) {
        float4 o = make_float4(c * acc[i][0], c * acc[i][1], c * acc[i][2], c * acc[i][3]);
        *(float4*)(outp + (size_t)i * SEQ) = o;
    }
}

// ---------------- row softmax in place (rows of 1024) ----------------
__global__ void softmax_kernel(float* __restrict__ attn) {
    size_t row = blockIdx.x;
    float* p = attn + row * SEQ;
    int t = threadIdx.x;
    float4 v = *(float4*)(p + t * 4);
    __shared__ float sh[8];
    // max
    float mx = fmaxf(fmaxf(v.x, v.y), fmaxf(v.z, v.w));
    #pragma unroll
    for (int o = 16; o; o >>= 1) mx = fmaxf(mx, __shfl_xor_sync(0xffffffffu, mx, o));
    if (!(t & 31)) sh[t >> 5] = mx;
    __syncthreads();
    float m = sh[0];
    #pragma unroll
    for (int i = 1; i < 8; i++) m = fmaxf(m, sh[i]);
    __syncthreads();
    // exp + sum
    float4 e;
    e.x = expf(v.x - m); e.y = expf(v.y - m);
    e.z = expf(v.z - m); e.w = expf(v.w - m);
    float s = e.x + e.y + e.z + e.w;
    #pragma unroll
    for (int o = 16; o; o >>= 1) s += __shfl_xor_sync(0xffffffffu, s, o);
    if (!(t & 31)) sh[t >> 5] = s;
    __syncthreads();
    float tot = 0.f;
    #pragma unroll
    for (int i = 0; i < 8; i++) tot += sh[i];
    float inv = 1.f / tot;
    e.x *= inv; e.y *= inv; e.z *= inv; e.w *= inv;
    *(float4*)(p + t * 4) = e;
}

// ---------------- out = attn @ V per head, written merged-head [B,S,H] ----------------
__global__ void __launch_bounds__(256) pv_kernel(
    const float* __restrict__ attn, const float* __restrict__ V, float* __restrict__ O)
{
    int bh = blockIdx.z;
    int b = bh / NHEAD, h = bh - b * NHEAD;
    const float* Ab = attn + (size_t)bh * SEQ * SEQ + (size_t)blockIdx.x * 64 * SEQ;
    const float* Vb = V + (size_t)b * SEQ * HID + h * HDIM;
    float* Ob       = O + (size_t)b * SEQ * HID + h * HDIM + (size_t)blockIdx.x * 64 * HID;
    __shared__ float Sa[16][68];
    __shared__ float Sv[16][64];
    int tid = threadIdx.x;
    int ar = tid >> 2, ac = (tid & 3) * 4;     // attn tile 64q x 16k
    int vr = tid >> 4, vc = (tid & 15) * 4;    // V tile 16k x 64d
    int tx = tid & 15, ty = tid >> 4;
    int qs = ty * 4, ds = tx * 4;
    float acc[4][4];
    #pragma unroll
    for (int i = 0; i < 4; i++)
        #pragma unroll
        for (int j = 0; j < 4; j++) acc[i][j] = 0.f;

    for (int k0 = 0; k0 < SEQ; k0 += 16) {
        float4 a4 = *(const float4*)(Ab + (size_t)ar * SEQ + k0 + ac);
        float4 v4 = *(const float4*)(Vb + (size_t)(k0 + vr) * HID + vc);
        __syncthreads();
        Sa[ac + 0][ar] = a4.x; Sa[ac + 1][ar] = a4.y;
        Sa[ac + 2][ar] = a4.z; Sa[ac + 3][ar] = a4.w;
        *(float4*)&Sv[vr][vc] = v4;
        __syncthreads();
        #pragma unroll
        for (int kk = 0; kk < 16; kk++) {
            float4 af = *(const float4*)&Sa[kk][qs];
            float4 vf = *(const float4*)&Sv[kk][ds];
            float aa[4] = {af.x, af.y, af.z, af.w};
            float vv[4] = {vf.x, vf.y, vf.z, vf.w};
            #pragma unroll
            for (int i = 0; i < 4; i++)
                #pragma unroll
                for (int j = 0; j < 4; j++)
                    acc[i][j] += aa[i] * vv[j];
        }
    }
    #pragma unroll
    for (int i = 0; i < 4; i++) {
        float4 o = make_float4(acc[i][0], acc[i][1], acc[i][2], acc[i][3]);
        *(float4*)(Ob + (size_t)(qs + i) * HID + ds) = o;
    }
}

// ---------------- launch ----------------
extern "C" void kernel_launch(void* const* d_in, const int* in_sizes, int n_in,
                              void* d_out, int out_size) {
    const float* hidden = (const float*)d_in[0];
    const float* ln1g = (const float*)d_in[1];
    const float* ln1b = (const float*)d_in[2];
    const float* Wq = (const float*)d_in[3];
    const float* bq = (const float*)d_in[4];
    const float* Wk = (const float*)d_in[5];
    const float* bk = (const float*)d_in[6];
    const float* Wv = (const float*)d_in[7];
    const float* bv = (const float*)d_in[8];
    const float* Wo = (const float*)d_in[9];
    const float* bo = (const float*)d_in[10];
    const float* lam = (const float*)d_in[11];
    const float* ln2g = (const float*)d_in[12];
    const float* ln2b = (const float*)d_in[13];
    const float* W1 = (const float*)d_in[14];
    const float* b1 = (const float*)d_in[15];
    const float* W2 = (const float*)d_in[16];
    const float* b2 = (const float*)d_in[17];

    float* out0 = (float*)d_out;
    float* attn = out0 + (size_t)MTOT * HID;  // [B,NH,S,S] follows [B,S,H]

    float *x, *q, *k, *v, *ao, *r1, *y, *ff;
    cudaGetSymbolAddress((void**)&x,  g_x);
    cudaGetSymbolAddress((void**)&q,  g_q);
    cudaGetSymbolAddress((void**)&k,  g_k);
    cudaGetSymbolAddress((void**)&v,  g_v);
    cudaGetSymbolAddress((void**)&ao, g_ao);
    cudaGetSymbolAddress((void**)&r1, g_r1);
    cudaGetSymbolAddress((void**)&y,  g_y);
    cudaGetSymbolAddress((void**)&ff, g_ff);

    dim3 gHH(HID / 128, MTOT / 128);   // (6,16)
    dim3 gF1(FFD / 128, MTOT / 128);   // (24,16)

    ln_kernel<<<MTOT, 256>>>(hidden, ln1g, ln1b, x);
    sgemm_kernel<<<gHH, 256>>>(x, Wq, bq, nullptr, q, MTOT, HID, HID, 0);
    sgemm_kernel<<<gHH, 256>>>(x, Wk, bk, nullptr, k, MTOT, HID, HID, 0);
    sgemm_kernel<<<gHH, 256>>>(x, Wv, bv, nullptr, v, MTOT, HID, HID, 0);
    dist_kernel<<<dim3(SEQ / 64, SEQ / 64, BHTOT), 256>>>(q, k, lam, attn);
    softmax_kernel<<<BHTOT * SEQ, 256>>>(attn);
    pv_kernel<<<dim3(SEQ / 64, 1, BHTOT), 256>>>(attn, v, ao);
    sgemm_kernel<<<gHH, 256>>>(ao, Wo, bo, hidden, r1, MTOT, HID, HID, 1);
    ln_kernel<<<MTOT, 256>>>(r1, ln2g, ln2b, y);
    sgemm_kernel<<<gF1, 256>>>(y, W1, b1, nullptr, ff, MTOT, FFD, HID, 2);
    sgemm_kernel<<<gHH, 256>>>(ff, W2, b2, r1, out0, MTOT, HID, FFD, 1);
}

// round 4
// speedup vs baseline: 1.0138x; 1.0138x over previous
#include <cuda_runtime.h>
#include <math.h>

#define SEQ   1024
#define BATCH 2
#define HID   768
#define NHEAD 12
#define HDIM  64
#define FFD   3072
#define MTOT  (BATCH*SEQ)   // 2048
#define BHTOT (BATCH*NHEAD) // 24

// ---------------- scratch (device globals: no allocation allowed) ----------------
__device__ float g_x [MTOT*HID];
__device__ float g_q [MTOT*HID];
__device__ float g_k [MTOT*HID];
__device__ float g_v [MTOT*HID];
__device__ float g_ao[MTOT*HID];
__device__ float g_r1[MTOT*HID];
__device__ float g_y [MTOT*HID];
__device__ float g_ff[MTOT*FFD];

// ---------------- LayerNorm: one block per row of 768 ----------------
__global__ void ln_kernel(const float* __restrict__ in, const float* __restrict__ g,
                          const float* __restrict__ b, float* __restrict__ out) {
    int row = blockIdx.x;
    const float* x = in + (size_t)row * HID;
    int t = threadIdx.x;
    float v0 = x[t], v1 = x[t + 256], v2 = x[t + 512];
    float s  = v0 + v1 + v2;
    float sq = v0 * v0 + v1 * v1 + v2 * v2;
    __shared__ float sh[16];
    #pragma unroll
    for (int o = 16; o; o >>= 1) {
        s  += __shfl_xor_sync(0xffffffffu, s,  o);
        sq += __shfl_xor_sync(0xffffffffu, sq, o);
    }
    int w = t >> 5, l = t & 31;
    if (!l) { sh[w] = s; sh[w + 8] = sq; }
    __syncthreads();
    if (w == 0) {
        float a = (l < 8) ? sh[l] : 0.f;
        float c = (l < 8) ? sh[l + 8] : 0.f;
        #pragma unroll
        for (int o = 4; o; o >>= 1) {
            a += __shfl_xor_sync(0xffffffffu, a, o);
            c += __shfl_xor_sync(0xffffffffu, c, o);
        }
        if (!l) { sh[0] = a; sh[1] = c; }
    }
    __syncthreads();
    float mean = sh[0] * (1.f / HID);
    float var  = sh[1] * (1.f / HID) - mean * mean;
    float rs   = rsqrtf(var + 1e-5f);
    float* o = out + (size_t)row * HID;
    o[t]       = (v0 - mean) * rs * g[t]       + b[t];
    o[t + 256] = (v1 - mean) * rs * g[t + 256] + b[t + 256];
    o[t + 512] = (v2 - mean) * rs * g[t + 512] + b[t + 512];
}

// ---------------- sgemm: C = A[M,K] @ B[K,N] + bias (+res / gelu) ----------------
// BM=BN=128, BK=8, 256 threads, 8x8 microtile. M%128==0, N%128==0, K%8==0 required.
// mode: 0 = +bias, 1 = +bias+res, 2 = gelu(+bias)
__global__ void __launch_bounds__(256) sgemm_kernel(
    const float* __restrict__ A, const float* __restrict__ Bm,
    const float* __restrict__ bias, const float* __restrict__ res,
    float* __restrict__ C, int M, int N, int K, int mode)
{
    __shared__ float As[8][128];
    __shared__ float Bs[8][128];
    int tid = threadIdx.x;
    int bm = blockIdx.y * 128, bn = blockIdx.x * 128;
    int arow = tid >> 1, acol = (tid & 1) * 4;
    int brow = tid >> 5, bcol = (tid & 31) * 4;
    int tx = tid & 15, ty = tid >> 4;
    int ms = ty * 8, ns = tx * 8;

    float acc[8][8];
    #pragma unroll
    for (int i = 0; i < 8; i++)
        #pragma unroll
        for (int j = 0; j < 8; j++) acc[i][j] = 0.f;

    const float* Ap = A  + (size_t)(bm + arow) * K + acol;
    const float* Bp = Bm + (size_t)brow * N + bn + bcol;

    for (int k0 = 0; k0 < K; k0 += 8) {
        float4 av = *(const float4*)(Ap + k0);
        float4 bv = *(const float4*)(Bp + (size_t)k0 * N);
        __syncthreads();
        As[acol + 0][arow] = av.x;
        As[acol + 1][arow] = av.y;
        As[acol + 2][arow] = av.z;
        As[acol + 3][arow] = av.w;
        *(float4*)&Bs[brow][bcol] = bv;
        __syncthreads();
        #pragma unroll
        for (int kk = 0; kk < 8; kk++) {
            float af[8], bf[8];
            *(float4*)(af)     = *(const float4*)&As[kk][ms];
            *(float4*)(af + 4) = *(const float4*)&As[kk][ms + 4];
            *(float4*)(bf)     = *(const float4*)&Bs[kk][ns];
            *(float4*)(bf + 4) = *(const float4*)&Bs[kk][ns + 4];
            #pragma unroll
            for (int i = 0; i < 8; i++)
                #pragma unroll
                for (int j = 0; j < 8; j++)
                    acc[i][j] += af[i] * bf[j];
        }
    }

    #pragma unroll
    for (int i = 0; i < 8; i++) {
        size_t crow = (size_t)(bm + ms + i);
        #pragma unroll
        for (int j0 = 0; j0 < 8; j0 += 4) {
            float o[4];
            #pragma unroll
            for (int jj = 0; jj < 4; jj++) {
                int col = bn + ns + j0 + jj;
                float val = acc[i][j0 + jj] + bias[col];
                if (mode == 1)      val += res[crow * N + col];
                else if (mode == 2) val = 0.5f * val * (1.f + erff(val * 0.70710678118654752f));
                o[jj] = val;
            }
            *(float4*)(C + crow * N + bn + ns + j0) = *(float4*)o;
        }
    }
}

// ---------------- L1 distance -> raw scores: -lam/8 * sum_d |q-k| ----------------
// 64x64 tile per block, 256 threads, 4x4 microtile; smem stored d-major.
__global__ void __launch_bounds__(256) dist_kernel(
    const float* __restrict__ Q, const float* __restrict__ K,
    const float* __restrict__ lamp, float* __restrict__ attn)
{
    __shared__ float Qs[64][68];
    __shared__ float Ks[64][68];
    int bh = blockIdx.z;
    int b = bh / NHEAD, h = bh - b * NHEAD;
    const float* Qb = Q + (size_t)b * SEQ * HID + h * HDIM + (size_t)blockIdx.y * 64 * HID;
    const float* Kb = K + (size_t)b * SEQ * HID + h * HDIM + (size_t)blockIdx.x * 64 * HID;
    int tid = threadIdx.x;
    int row = tid >> 2, dg = (tid & 3) * 16;
    #pragma unroll
    for (int i = 0; i < 4; i++) {
        float4 qv = *(const float4*)(Qb + (size_t)row * HID + dg + i * 4);
        float4 kv = *(const float4*)(Kb + (size_t)row * HID + dg + i * 4);
        Qs[dg + i*4 + 0][row] = qv.x; Qs[dg + i*4 + 1][row] = qv.y;
        Qs[dg + i*4 + 2][row] = qv.z; Qs[dg + i*4 + 3][row] = qv.w;
        Ks[dg + i*4 + 0][row] = kv.x; Ks[dg + i*4 + 1][row] = kv.y;
        Ks[dg + i*4 + 2][row] = kv.z; Ks[dg + i*4 + 3][row] = kv.w;
    }
    __syncthreads();
    int tx = tid & 15, ty = tid >> 4;
    int qs = ty * 4, ks = tx * 4;
    float acc[4][4];
    #pragma unroll
    for (int i = 0; i < 4; i++)
        #pragma unroll
        for (int j = 0; j < 4; j++) acc[i][j] = 0.f;
    #pragma unroll 16
    for (int d = 0; d < HDIM; d++) {
        float4 qf = *(const float4*)&Qs[d][qs];
        float4 kf = *(const float4*)&Ks[d][ks];
        float qa[4] = {qf.x, qf.y, qf.z, qf.w};
        float ka[4] = {kf.x, kf.y, kf.z, kf.w};
        #pragma unroll
        for (int i = 0; i < 4; i++)
            #pragma unroll
            for (int j = 0; j < 4; j++)
                acc[i][j] += fabsf(qa[i] - ka[j]);
    }
    float c = -(*lamp) * 0.125f;  // scale = 1/sqrt(64)
    float* outp = attn + (size_t)bh * SEQ * SEQ
                + ((size_t)blockIdx.y * 64 + qs) * SEQ + blockIdx.x * 64 + ks;
    #pragma unroll
    for (int i = 0; i < 4; i++) {
        float4 o = make_float4(c * acc[i][0], c * acc[i][1], c * acc[i][2], c * acc[i][3]);
        *(float4*)(outp + (size_t)i * SEQ) = o;
    }
}

// ---------------- row softmax in place (rows of 1024) ----------------
__global__ void softmax_kernel(float* __restrict__ attn) {
    size_t row = blockIdx.x;
    float* p = attn + row * SEQ;
    int t = threadIdx.x;
    float4 v = *(float4*)(p + t * 4);
    __shared__ float sh[8];
    // max
    float mx = fmaxf(fmaxf(v.x, v.y), fmaxf(v.z, v.w));
    #pragma unroll
    for (int o = 16; o; o >>= 1) mx = fmaxf(mx, __shfl_xor_sync(0xffffffffu, mx, o));
    if (!(t & 31)) sh[t >> 5] = mx;
    __syncthreads();
    float m = sh[0];
    #pragma unroll
    for (int i = 1; i < 8; i++) m = fmaxf(m, sh[i]);
    __syncthreads();
    // exp + sum
    float4 e;
    e.x = expf(v.x - m); e.y = expf(v.y - m);
    e.z = expf(v.z - m); e.w = expf(v.w - m);
    float s = e.x + e.y + e.z + e.w;
    #pragma unroll
    for (int o = 16; o; o >>= 1) s += __shfl_xor_sync(0xffffffffu, s, o);
    if (!(t & 31)) sh[t >> 5] = s;
    __syncthreads();
    float tot = 0.f;
    #pragma unroll
    for (int i = 0; i < 8; i++) tot += sh[i];
    float inv = 1.f / tot;
    e.x *= inv; e.y *= inv; e.z *= inv; e.w *= inv;
    *(float4*)(p + t * 4) = e;
}

// ---------------- out = attn @ V per head, written merged-head [B,S,H] ----------------
__global__ void __launch_bounds__(256) pv_kernel(
    const float* __restrict__ attn, const float* __restrict__ V, float* __restrict__ O)
{
    int bh = blockIdx.z;
    int b = bh / NHEAD, h = bh - b * NHEAD;
    const float* Ab = attn + (size_t)bh * SEQ * SEQ + (size_t)blockIdx.x * 64 * SEQ;
    const float* Vb = V + (size_t)b * SEQ * HID + h * HDIM;
    float* Ob       = O + (size_t)b * SEQ * HID + h * HDIM + (size_t)blockIdx.x * 64 * HID;
    __shared__ float Sa[16][68];
    __shared__ float Sv[16][64];
    int tid = threadIdx.x;
    int ar = tid >> 2, ac = (tid & 3) * 4;     // attn tile 64q x 16k
    int vr = tid >> 4, vc = (tid & 15) * 4;    // V tile 16k x 64d
    int tx = tid & 15, ty = tid >> 4;
    int qs = ty * 4, ds = tx * 4;
    float acc[4][4];
    #pragma unroll
    for (int i = 0; i < 4; i++)
        #pragma unroll
        for (int j = 0; j < 4; j++) acc[i][j] = 0.f;

    for (int k0 = 0; k0 < SEQ; k0 += 16) {
        float4 a4 = *(const float4*)(Ab + (size_t)ar * SEQ + k0 + ac);
        float4 v4 = *(const float4*)(Vb + (size_t)(k0 + vr) * HID + vc);
        __syncthreads();
        Sa[ac + 0][ar] = a4.x; Sa[ac + 1][ar] = a4.y;
        Sa[ac + 2][ar] = a4.z; Sa[ac + 3][ar] = a4.w;
        *(float4*)&Sv[vr][vc] = v4;
        __syncthreads();
        #pragma unroll
        for (int kk = 0; kk < 16; kk++) {
            float4 af = *(const float4*)&Sa[kk][qs];
            float4 vf = *(const float4*)&Sv[kk][ds];
            float aa[4] = {af.x, af.y, af.z, af.w};
            float vv[4] = {vf.x, vf.y, vf.z, vf.w};
            #pragma unroll
            for (int i = 0; i < 4; i++)
                #pragma unroll
                for (int j = 0; j < 4; j++)
                    acc[i][j] += aa[i] * vv[j];
        }
    }
    #pragma unroll
    for (int i = 0; i < 4; i++) {
        float4 o = make_float4(acc[i][0], acc[i][1], acc[i][2], acc[i][3]);
        *(float4*)(Ob + (size_t)(qs + i) * HID + ds) = o;
    }
}

// ---------------- launch ----------------
extern "C" void kernel_launch(void* const* d_in, const int* in_sizes, int n_in,
                              void* d_out, int out_size) {
    const float* hidden = (const float*)d_in[0];
    const float* ln1g = (const float*)d_in[1];
    const float* ln1b = (const float*)d_in[2];
    const float* Wq = (const float*)d_in[3];
    const float* bq = (const float*)d_in[4];
    const float* Wk = (const float*)d_in[5];
    const float* bk = (const float*)d_in[6];
    const float* Wv = (const float*)d_in[7];
    const float* bv = (const float*)d_in[8];
    const float* Wo = (const float*)d_in[9];
    const float* bo = (const float*)d_in[10];
    const float* lam = (const float*)d_in[11];
    const float* ln2g = (const float*)d_in[12];
    const float* ln2b = (const float*)d_in[13];
    const float* W1 = (const float*)d_in[14];
    const float* b1 = (const float*)d_in[15];
    const float* W2 = (const float*)d_in[16];
    const float* b2 = (const float*)d_in[17];

    float* out0 = (float*)d_out;
    float* attn = out0 + (size_t)MTOT * HID;  // [B,NH,S,S] follows [B,S,H]

    float *x, *q, *k, *v, *ao, *r1, *y, *ff;
    cudaGetSymbolAddress((void**)&x,  g_x);
    cudaGetSymbolAddress((void**)&q,  g_q);
    cudaGetSymbolAddress((void**)&k,  g_k);
    cudaGetSymbolAddress((void**)&v,  g_v);
    cudaGetSymbolAddress((void**)&ao, g_ao);
    cudaGetSymbolAddress((void**)&r1, g_r1);
    cudaGetSymbolAddress((void**)&y,  g_y);
    cudaGetSymbolAddress((void**)&ff, g_ff);

    dim3 gHH(HID / 128, MTOT / 128);   // (6,16)
    dim3 gF1(FFD / 128, MTOT / 128);   // (24,16)

    ln_kernel<<<MTOT, 256>>>(hidden, ln1g, ln1b, x);
    sgemm_kernel<<<gHH, 256>>>(x, Wq, bq, nullptr, q, MTOT, HID, HID, 0);
    sgemm_kernel<<<gHH, 256>>>(x, Wk, bk, nullptr, k, MTOT, HID, HID, 0);
    sgemm_kernel<<<gHH, 256>>>(x, Wv, bv, nullptr, v, MTOT, HID, HID, 0);
    dist_kernel<<<dim3(SEQ / 64, SEQ / 64, BHTOT), 256>>>(q, k, lam, attn);
    softmax_kernel<<<BHTOT * SEQ, 256>>>(attn);
    pv_kernel<<<dim3(SEQ / 64, 1, BHTOT), 256>>>(attn, v, ao);
    sgemm_kernel<<<gHH, 256>>>(ao, Wo, bo, hidden, r1, MTOT, HID, HID, 1);
    ln_kernel<<<MTOT, 256>>>(r1, ln2g, ln2b, y);
    sgemm_kernel<<<gF1, 256>>>(y, W1, b1, nullptr, ff, MTOT, FFD, HID, 2);
    sgemm_kernel<<<gHH, 256>>>(ff, W2, b2, r1, out0, MTOT, HID, FFD, 1);
}

// round 6
// speedup vs baseline: 1.6928x; 1.6698x over previous
#include <cuda_runtime.h>
#include <math.h>

#define SEQ   1024
#define BATCH 2
#define HID   768
#define NHEAD 12
#define HDIM  64
#define FFD   3072
#define MTOT  (BATCH*SEQ)   // 2048
#define BHTOT (BATCH*NHEAD) // 24

// ---------------- scratch (device globals: no allocation allowed) ----------------
__device__ float g_x [MTOT*HID];
__device__ float g_q [MTOT*HID];
__device__ float g_k [MTOT*HID];
__device__ float g_v [MTOT*HID];
__device__ float g_ao[MTOT*HID];
__device__ float g_r1[MTOT*HID];
__device__ float g_y [MTOT*HID];
__device__ float g_ff[MTOT*FFD];

// ---------------- helpers ----------------
__device__ __forceinline__ unsigned long long f2add(unsigned long long a, unsigned long long b) {
    unsigned long long r;
    asm("add.rn.f32x2 %0, %1, %2;" : "=l"(r) : "l"(a), "l"(b));
    return r;
}

__device__ __forceinline__ float gelu1(float v) {
    return 0.5f * v * (1.f + erff(v * 0.70710678118654752f));
}

// ---------------- LayerNorm: one block per row of 768 ----------------
__global__ void ln_kernel(const float* __restrict__ in, const float* __restrict__ g,
                          const float* __restrict__ b, float* __restrict__ out) {
    int row = blockIdx.x;
    const float* x = in + (size_t)row * HID;
    int t = threadIdx.x;
    float v0 = x[t], v1 = x[t + 256], v2 = x[t + 512];
    float s  = v0 + v1 + v2;
    float sq = v0 * v0 + v1 * v1 + v2 * v2;
    __shared__ float sh[16];
    #pragma unroll
    for (int o = 16; o; o >>= 1) {
        s  += __shfl_xor_sync(0xffffffffu, s,  o);
        sq += __shfl_xor_sync(0xffffffffu, sq, o);
    }
    int w = t >> 5, l = t & 31;
    if (!l) { sh[w] = s; sh[w + 8] = sq; }
    __syncthreads();
    if (w == 0) {
        float a = (l < 8) ? sh[l] : 0.f;
        float c = (l < 8) ? sh[l + 8] : 0.f;
        #pragma unroll
        for (int o = 4; o; o >>= 1) {
            a += __shfl_xor_sync(0xffffffffu, a, o);
            c += __shfl_xor_sync(0xffffffffu, c, o);
        }
        if (!l) { sh[0] = a; sh[1] = c; }
    }
    __syncthreads();
    float mean = sh[0] * (1.f / HID);
    float var  = sh[1] * (1.f / HID) - mean * mean;
    float rs   = rsqrtf(var + 1e-5f);
    float* o = out + (size_t)row * HID;
    o[t]       = (v0 - mean) * rs * g[t]       + b[t];
    o[t + 256] = (v1 - mean) * rs * g[t + 256] + b[t + 256];
    o[t + 512] = (v2 - mean) * rs * g[t + 512] + b[t + 512];
}

// ---------------- core: 128x64 tile, BK=16, double-buffered, 8x4 microtile ----------------
// A: pointer to A[bm][kStart] with leading dim lda; B: pointer to B[kStart][bn], ld ldb.
// kLen must be a multiple of 16 and >= 32.
__device__ __forceinline__ void gemm_tile(
    const float* __restrict__ A, int lda,
    const float* __restrict__ B, int ldb,
    int kLen,
    float (*As)[16][132], float (*Bs)[16][64],
    float (&acc)[8][4])
{
    int tid = threadIdx.x;
    int ar = tid >> 1, ac = (tid & 1) * 8;
    int br = tid >> 4, bc = (tid & 15) * 4;
    int ms = (tid >> 4) * 8, ns = (tid & 15) * 4;

    const float* Ap = A + (size_t)ar * lda + ac;
    const float* Bp = B + (size_t)br * ldb + bc;

    // prefetch chunk 0 -> smem buf 0
    {
        float4 av0 = *(const float4*)(Ap);
        float4 av1 = *(const float4*)(Ap + 4);
        float4 bv  = *(const float4*)(Bp);
        As[0][ac + 0][ar] = av0.x; As[0][ac + 1][ar] = av0.y;
        As[0][ac + 2][ar] = av0.z; As[0][ac + 3][ar] = av0.w;
        As[0][ac + 4][ar] = av1.x; As[0][ac + 5][ar] = av1.y;
        As[0][ac + 6][ar] = av1.z; As[0][ac + 7][ar] = av1.w;
        *(float4*)&Bs[0][br][bc] = bv;
    }
    __syncthreads();

    int kc = kLen >> 4;
    for (int c = 1; c < kc; c++) {
        const float* Ac = Ap + c * 16;
        float4 av0 = *(const float4*)(Ac);
        float4 av1 = *(const float4*)(Ac + 4);
        float4 bv  = *(const float4*)(Bp + (size_t)(c * 16) * ldb);
        int pb = (c - 1) & 1, nb = c & 1;
        #pragma unroll
        for (int kk = 0; kk < 16; kk++) {
            float af[8], bf[4];
            *(float4*)(af)     = *(const float4*)&As[pb][kk][ms];
            *(float4*)(af + 4) = *(const float4*)&As[pb][kk][ms + 4];
            *(float4*)(bf)     = *(const float4*)&Bs[pb][kk][ns];
            #pragma unroll
            for (int i = 0; i < 8; i++)
                #pragma unroll
                for (int j = 0; j < 4; j++)
                    acc[i][j] += af[i] * bf[j];
        }
        As[nb][ac + 0][ar] = av0.x; As[nb][ac + 1][ar] = av0.y;
        As[nb][ac + 2][ar] = av0.z; As[nb][ac + 3][ar] = av0.w;
        As[nb][ac + 4][ar] = av1.x; As[nb][ac + 5][ar] = av1.y;
        As[nb][ac + 6][ar] = av1.z; As[nb][ac + 7][ar] = av1.w;
        *(float4*)&Bs[nb][br][bc] = bv;
        __syncthreads();
    }
    int lb = (kc - 1) & 1;
    #pragma unroll
    for (int kk = 0; kk < 16; kk++) {
        float af[8], bf[4];
        *(float4*)(af)     = *(const float4*)&As[lb][kk][ms];
        *(float4*)(af + 4) = *(const float4*)&As[lb][kk][ms + 4];
        *(float4*)(bf)     = *(const float4*)&Bs[lb][kk][ns];
        #pragma unroll
        for (int i = 0; i < 8; i++)
            #pragma unroll
            for (int j = 0; j < 4; j++)
                acc[i][j] += af[i] * bf[j];
    }
}

// ---------------- fused QKV: grid (36,16); blockIdx.x/12 selects matrix ----------------
__global__ void __launch_bounds__(256, 2) qkv_kernel(
    const float* __restrict__ x,
    const float* __restrict__ Wq, const float* __restrict__ Wk, const float* __restrict__ Wv,
    const float* __restrict__ bq, const float* __restrict__ bk, const float* __restrict__ bv,
    float* __restrict__ q, float* __restrict__ k, float* __restrict__ v)
{
    __shared__ float As[2][16][132];
    __shared__ float Bs[2][16][64];
    int sel = blockIdx.x / 12;
    int bn  = (blockIdx.x % 12) * 64;
    int bm  = blockIdx.y * 128;
    const float* B    = sel == 0 ? Wq : (sel == 1 ? Wk : Wv);
    const float* bias = sel == 0 ? bq : (sel == 1 ? bk : bv);
    float* C          = sel == 0 ? q  : (sel == 1 ? k  : v);
    float acc[8][4] = {};
    gemm_tile(x + (size_t)bm * HID, HID, B + bn, HID, HID, As, Bs, acc);
    int tid = threadIdx.x;
    int ms = (tid >> 4) * 8, ns = (tid & 15) * 4;
    float4 bi = *(const float4*)(bias + bn + ns);
    #pragma unroll
    for (int i = 0; i < 8; i++) {
        float4 o = make_float4(acc[i][0] + bi.x, acc[i][1] + bi.y,
                               acc[i][2] + bi.z, acc[i][3] + bi.w);
        *(float4*)(C + (size_t)(bm + ms + i) * HID + bn + ns) = o;
    }
}

// ---------------- generic gemm: grid (N/64, M/128); mode 0=+bias 2=gelu(+bias) ----------------
__global__ void __launch_bounds__(256, 2) gemm_kernel(
    const float* __restrict__ A, int K,
    const float* __restrict__ B, int N,
    const float* __restrict__ bias,
    float* __restrict__ C, int mode)
{
    __shared__ float As[2][16][132];
    __shared__ float Bs[2][16][64];
    int bm = blockIdx.y * 128, bn = blockIdx.x * 64;
    float acc[8][4] = {};
    gemm_tile(A + (size_t)bm * K, K, B + bn, N, K, As, Bs, acc);
    int tid = threadIdx.x;
    int ms = (tid >> 4) * 8, ns = (tid & 15) * 4;
    float4 bi = *(const float4*)(bias + bn + ns);
    #pragma unroll
    for (int i = 0; i < 8; i++) {
        float o0 = acc[i][0] + bi.x, o1 = acc[i][1] + bi.y;
        float o2 = acc[i][2] + bi.z, o3 = acc[i][3] + bi.w;
        if (mode == 2) { o0 = gelu1(o0); o1 = gelu1(o1); o2 = gelu1(o2); o3 = gelu1(o3); }
        float4 o = make_float4(o0, o1, o2, o3);
        *(float4*)(C + (size_t)(bm + ms + i) * N + bn + ns) = o;
    }
}

// ---------------- split-K=2 gemm: grid (N/64, M/128, 2) -> raw partials ----------------
__global__ void __launch_bounds__(256, 2) gemm_split_kernel(
    const float* __restrict__ A, int K,
    const float* __restrict__ B, int N,
    float* __restrict__ P1, float* __restrict__ P2)
{
    __shared__ float As[2][16][132];
    __shared__ float Bs[2][16][64];
    int bm = blockIdx.y * 128, bn = blockIdx.x * 64;
    int half = K >> 1, z = blockIdx.z;
    float acc[8][4] = {};
    gemm_tile(A + (size_t)bm * K + z * half, K,
              B + (size_t)(z * half) * N + bn, N, half, As, Bs, acc);
    float* C = z ? P2 : P1;
    int tid = threadIdx.x;
    int ms = (tid >> 4) * 8, ns = (tid & 15) * 4;
    #pragma unroll
    for (int i = 0; i < 8; i++) {
        float4 o = make_float4(acc[i][0], acc[i][1], acc[i][2], acc[i][3]);
        *(float4*)(C + (size_t)(bm + ms + i) * N + bn + ns) = o;
    }
}

// ---------------- epilogue: out = p1 + p2 + bias + res ----------------
__global__ void epi_kernel(const float* __restrict__ p1, const float* __restrict__ p2,
                           const float* __restrict__ bias, const float* __restrict__ res,
                           float* __restrict__ out)
{
    int idx = (blockIdx.x * 256 + threadIdx.x) * 4;
    int col = idx % HID;
    float4 a  = *(const float4*)(p1 + idx);
    float4 b  = *(const float4*)(p2 + idx);
    float4 r  = *(const float4*)(res + idx);
    float4 bi = *(const float4*)(bias + col);
    float4 o = make_float4(a.x + b.x + r.x + bi.x, a.y + b.y + r.y + bi.y,
                           a.z + b.z + r.z + bi.z, a.w + b.w + r.w + bi.w);
    *(float4*)(out + idx) = o;
}

// ---------------- L1 distance (f32x2 packed): tile 128(q) x 64(k), 8x4 microtile ----------------
__global__ void __launch_bounds__(256) dist_kernel(
    const float* __restrict__ Q, const float* __restrict__ Km,
    const float* __restrict__ lamp, float* __restrict__ attn)
{
    __shared__ unsigned long long Qs[32][128];   // [d-pair][q-row]
    __shared__ unsigned long long Ks[32][64];    // negated K
    int bh = blockIdx.z, b = bh / NHEAD, h = bh - b * NHEAD;
    int qbase = blockIdx.y * 128, kbase = blockIdx.x * 64;
    const float* Qb = Q  + (size_t)b * SEQ * HID + h * HDIM + (size_t)qbase * HID;
    const float* Kb = Km + (size_t)b * SEQ * HID + h * HDIM + (size_t)kbase * HID;
    int tid = threadIdx.x;

    union F2U { float2 f; unsigned long long u; };
    {   // Q: 128 rows, each thread loads 32 dims of one row
        int row = tid >> 1, hh = (tid & 1) * 32;
        #pragma unroll
        for (int i = 0; i < 8; i++) {
            float4 qv = *(const float4*)(Qb + (size_t)row * HID + hh + i * 4);
            F2U t;
            t.f = make_float2(qv.x, qv.y); Qs[(hh >> 1) + i * 2][row]     = t.u;
            t.f = make_float2(qv.z, qv.w); Qs[(hh >> 1) + i * 2 + 1][row] = t.u;
        }
    }
    {   // K: 64 rows, each thread loads 16 dims of one row (negated)
        int row = tid >> 2, kq = (tid & 3) * 16;
        #pragma unroll
        for (int i = 0; i < 4; i++) {
            float4 kv = *(const float4*)(Kb + (size_t)row * HID + kq + i * 4);
            F2U t;
            t.f = make_float2(-kv.x, -kv.y); Ks[(kq >> 1) + i * 2][row]     = t.u;
            t.f = make_float2(-kv.z, -kv.w); Ks[(kq >> 1) + i * 2 + 1][row] = t.u;
        }
    }
    __syncthreads();

    int tx = tid & 15, ty = tid >> 4;
    int qs = ty * 8, ks = tx * 4;
    unsigned long long acc[8][4] = {};
    const unsigned long long MASK = 0x7FFFFFFF7FFFFFFFull;
    #pragma unroll 4
    for (int d = 0; d < 32; d++) {
        unsigned long long qv[8], kv[4];
        *(ulonglong2*)&qv[0] = *(const ulonglong2*)&Qs[d][qs];
        *(ulonglong2*)&qv[2] = *(const ulonglong2*)&Qs[d][qs + 2];
        *(ulonglong2*)&qv[4] = *(const ulonglong2*)&Qs[d][qs + 4];
        *(ulonglong2*)&qv[6] = *(const ulonglong2*)&Qs[d][qs + 6];
        *(ulonglong2*)&kv[0] = *(const ulonglong2*)&Ks[d][ks];
        *(ulonglong2*)&kv[2] = *(const ulonglong2*)&Ks[d][ks + 2];
        #pragma unroll
        for (int i = 0; i < 8; i++)
            #pragma unroll
            for (int j = 0; j < 4; j++) {
                unsigned long long df = f2add(qv[i], kv[j]) & MASK;
                acc[i][j] = f2add(acc[i][j], df);
            }
    }
    float c = -(*lamp) * 0.125f;   // scale = 1/sqrt(64)
    float* outp = attn + (size_t)bh * SEQ * SEQ + (size_t)(qbase + qs) * SEQ + kbase + ks;
    #pragma unroll
    for (int i = 0; i < 8; i++) {
        float4 o;
        F2U t;
        t.u = acc[i][0]; o.x = c * (t.f.x + t.f.y);
        t.u = acc[i][1]; o.y = c * (t.f.x + t.f.y);
        t.u = acc[i][2]; o.z = c * (t.f.x + t.f.y);
        t.u = acc[i][3]; o.w = c * (t.f.x + t.f.y);
        *(float4*)(outp + (size_t)i * SEQ) = o;
    }
}

// ---------------- row softmax in place (rows of 1024) ----------------
__global__ void softmax_kernel(float* __restrict__ attn) {
    size_t row = blockIdx.x;
    float* p = attn + row * SEQ;
    int t = threadIdx.x;
    float4 v = *(float4*)(p + t * 4);
    __shared__ float sh[8];
    float mx = fmaxf(fmaxf(v.x, v.y), fmaxf(v.z, v.w));
    #pragma unroll
    for (int o = 16; o; o >>= 1) mx = fmaxf(mx, __shfl_xor_sync(0xffffffffu, mx, o));
    if (!(t & 31)) sh[t >> 5] = mx;
    __syncthreads();
    float m = sh[0];
    #pragma unroll
    for (int i = 1; i < 8; i++) m = fmaxf(m, sh[i]);
    __syncthreads();
    float4 e;
    e.x = expf(v.x - m); e.y = expf(v.y - m);
    e.z = expf(v.z - m); e.w = expf(v.w - m);
    float s = e.x + e.y + e.z + e.w;
    #pragma unroll
    for (int o = 16; o; o >>= 1) s += __shfl_xor_sync(0xffffffffu, s, o);
    if (!(t & 31)) sh[t >> 5] = s;
    __syncthreads();
    float tot = 0.f;
    #pragma unroll
    for (int i = 0; i < 8; i++) tot += sh[i];
    float inv = 1.f / tot;
    e.x *= inv; e.y *= inv; e.z *= inv; e.w *= inv;
    *(float4*)(p + t * 4) = e;
}

// ---------------- out = attn @ V per head: grid (8,1,24), 128x64 engine ----------------
__global__ void __launch_bounds__(256, 2) pv_kernel(
    const float* __restrict__ attn, const float* __restrict__ V, float* __restrict__ O)
{
    __shared__ float As[2][16][132];
    __shared__ float Bs[2][16][64];
    int bh = blockIdx.z, b = bh / NHEAD, h = bh - b * NHEAD;
    int bm = blockIdx.x * 128;
    const float* A  = attn + (size_t)bh * SEQ * SEQ + (size_t)bm * SEQ;
    const float* Bv = V + (size_t)b * SEQ * HID + h * HDIM;
    float acc[8][4] = {};
    gemm_tile(A, SEQ, Bv, HID, SEQ, As, Bs, acc);
    float* Ob = O + (size_t)b * SEQ * HID + h * HDIM + (size_t)bm * HID;
    int tid = threadIdx.x;
    int ms = (tid >> 4) * 8, ns = (tid & 15) * 4;
    #pragma unroll
    for (int i = 0; i < 8; i++) {
        float4 o = make_float4(acc[i][0], acc[i][1], acc[i][2], acc[i][3]);
        *(float4*)(Ob + (size_t)(ms + i) * HID + ns) = o;
    }
}

// ---------------- launch ----------------
extern "C" void kernel_launch(void* const* d_in, const int* in_sizes, int n_in,
                              void* d_out, int out_size) {
    const float* hidden = (const float*)d_in[0];
    const float* ln1g = (const float*)d_in[1];
    const float* ln1b = (const float*)d_in[2];
    const float* Wq = (const float*)d_in[3];
    const float* bq = (const float*)d_in[4];
    const float* Wk = (const float*)d_in[5];
    const float* bk = (const float*)d_in[6];
    const float* Wv = (const float*)d_in[7];
    const float* bv = (const float*)d_in[8];
    const float* Wo = (const float*)d_in[9];
    const float* bo = (const float*)d_in[10];
    const float* lam = (const float*)d_in[11];
    const float* ln2g = (const float*)d_in[12];
    const float* ln2b = (const float*)d_in[13];
    const float* W1 = (const float*)d_in[14];
    const float* b1 = (const float*)d_in[15];
    const float* W2 = (const float*)d_in[16];
    const float* b2 = (const float*)d_in[17];

    float* out0 = (float*)d_out;
    float* attn = out0 + (size_t)MTOT * HID;  // [B,NH,S,S] follows [B,S,H]

    float *x, *q, *k, *v, *ao, *r1, *y, *ff;
    cudaGetSymbolAddress((void**)&x,  g_x);
    cudaGetSymbolAddress((void**)&q,  g_q);
    cudaGetSymbolAddress((void**)&k,  g_k);
    cudaGetSymbolAddress((void**)&v,  g_v);
    cudaGetSymbolAddress((void**)&ao, g_ao);
    cudaGetSymbolAddress((void**)&r1, g_r1);
    cudaGetSymbolAddress((void**)&y,  g_y);
    cudaGetSymbolAddress((void**)&ff, g_ff);

    int epiGrid = (MTOT * HID) / (256 * 4);   // 1536

    ln_kernel<<<MTOT, 256>>>(hidden, ln1g, ln1b, x);
    qkv_kernel<<<dim3(36, 16), 256>>>(x, Wq, Wk, Wv, bq, bk, bv, q, k, v);
    dist_kernel<<<dim3(SEQ / 64, SEQ / 128, BHTOT), 256>>>(q, k, lam, attn);
    softmax_kernel<<<BHTOT * SEQ, 256>>>(attn);
    pv_kernel<<<dim3(SEQ / 128, 1, BHTOT), 256>>>(attn, v, ao);
    // Wo with split-K=2: partials in g_x (x free) and g_ff (free until FF1)
    gemm_split_kernel<<<dim3(12, 16, 2), 256>>>(ao, HID, Wo, HID, x, ff);
    epi_kernel<<<epiGrid, 256>>>(x, ff, bo, hidden, r1);
    ln_kernel<<<MTOT, 256>>>(r1, ln2g, ln2b, y);
    gemm_kernel<<<dim3(48, 16), 256>>>(y, HID, W1, FFD, b1, ff, 2);          // gelu (N=3072 -> 48 blocks)
    // FF2 with split-K=2: partials in g_x and g_q (both free now)
    gemm_split_kernel<<<dim3(12, 16, 2), 256>>>(ff, FFD, W2, HID, x, q);
    epi_kernel<<<epiGrid, 256>>>(x, q, b2, r1, out0);
}

// round 7
// speedup vs baseline: 1.6928x; 1.0000x over previous
#include <cuda_runtime.h>
#include <math.h>

#define SEQ   1024
#define BATCH 2
#define HID   768
#define NHEAD 12
#define HDIM  64
#define FFD   3072
#define MTOT  (BATCH*SEQ)   // 2048
#define BHTOT (BATCH*NHEAD) // 24

// ---------------- scratch (device globals: no allocation allowed) ----------------
__device__ float g_x [MTOT*HID];
__device__ float g_q [MTOT*HID];
__device__ float g_k [MTOT*HID];
__device__ float g_v [MTOT*HID];
__device__ float g_ao[MTOT*HID];
__device__ float g_r1[MTOT*HID];
__device__ float g_y [MTOT*HID];
__device__ float g_ff[MTOT*FFD];

// ---------------- helpers ----------------
__device__ __forceinline__ unsigned long long f2add(unsigned long long a, unsigned long long b) {
    unsigned long long r;
    asm("add.rn.f32x2 %0, %1, %2;" : "=l"(r) : "l"(a), "l"(b));
    return r;
}

__device__ __forceinline__ float gelu1(float v) {
    return 0.5f * v * (1.f + erff(v * 0.70710678118654752f));
}

// ---------------- LayerNorm: one block per row of 768 ----------------
__global__ void ln_kernel(const float* __restrict__ in, const float* __restrict__ g,
                          const float* __restrict__ b, float* __restrict__ out) {
    int row = blockIdx.x;
    const float* x = in + (size_t)row * HID;
    int t = threadIdx.x;
    float v0 = x[t], v1 = x[t + 256], v2 = x[t + 512];
    float s  = v0 + v1 + v2;
    float sq = v0 * v0 + v1 * v1 + v2 * v2;
    __shared__ float sh[16];
    #pragma unroll
    for (int o = 16; o; o >>= 1) {
        s  += __shfl_xor_sync(0xffffffffu, s,  o);
        sq += __shfl_xor_sync(0xffffffffu, sq, o);
    }
    int w = t >> 5, l = t & 31;
    if (!l) { sh[w] = s; sh[w + 8] = sq; }
    __syncthreads();
    if (w == 0) {
        float a = (l < 8) ? sh[l] : 0.f;
        float c = (l < 8) ? sh[l + 8] : 0.f;
        #pragma unroll
        for (int o = 4; o; o >>= 1) {
            a += __shfl_xor_sync(0xffffffffu, a, o);
            c += __shfl_xor_sync(0xffffffffu, c, o);
        }
        if (!l) { sh[0] = a; sh[1] = c; }
    }
    __syncthreads();
    float mean = sh[0] * (1.f / HID);
    float var  = sh[1] * (1.f / HID) - mean * mean;
    float rs   = rsqrtf(var + 1e-5f);
    float* o = out + (size_t)row * HID;
    o[t]       = (v0 - mean) * rs * g[t]       + b[t];
    o[t + 256] = (v1 - mean) * rs * g[t + 256] + b[t + 256];
    o[t + 512] = (v2 - mean) * rs * g[t + 512] + b[t + 512];
}

// ---------------- core: 128x64 tile, BK=16, double-buffered, 8x4 microtile ----------------
// A: pointer to A[bm][kStart] with leading dim lda; B: pointer to B[kStart][bn], ld ldb.
// kLen must be a multiple of 16 and >= 32.
__device__ __forceinline__ void gemm_tile(
    const float* __restrict__ A, int lda,
    const float* __restrict__ B, int ldb,
    int kLen,
    float (*As)[16][132], float (*Bs)[16][64],
    float (&acc)[8][4])
{
    int tid = threadIdx.x;
    int ar = tid >> 1, ac = (tid & 1) * 8;
    int br = tid >> 4, bc = (tid & 15) * 4;
    int ms = (tid >> 4) * 8, ns = (tid & 15) * 4;

    const float* Ap = A + (size_t)ar * lda + ac;
    const float* Bp = B + (size_t)br * ldb + bc;

    // prefetch chunk 0 -> smem buf 0
    {
        float4 av0 = *(const float4*)(Ap);
        float4 av1 = *(const float4*)(Ap + 4);
        float4 bv  = *(const float4*)(Bp);
        As[0][ac + 0][ar] = av0.x; As[0][ac + 1][ar] = av0.y;
        As[0][ac + 2][ar] = av0.z; As[0][ac + 3][ar] = av0.w;
        As[0][ac + 4][ar] = av1.x; As[0][ac + 5][ar] = av1.y;
        As[0][ac + 6][ar] = av1.z; As[0][ac + 7][ar] = av1.w;
        *(float4*)&Bs[0][br][bc] = bv;
    }
    __syncthreads();

    int kc = kLen >> 4;
    for (int c = 1; c < kc; c++) {
        const float* Ac = Ap + c * 16;
        float4 av0 = *(const float4*)(Ac);
        float4 av1 = *(const float4*)(Ac + 4);
        float4 bv  = *(const float4*)(Bp + (size_t)(c * 16) * ldb);
        int pb = (c - 1) & 1, nb = c & 1;
        #pragma unroll
        for (int kk = 0; kk < 16; kk++) {
            float af[8], bf[4];
            *(float4*)(af)     = *(const float4*)&As[pb][kk][ms];
            *(float4*)(af + 4) = *(const float4*)&As[pb][kk][ms + 4];
            *(float4*)(bf)     = *(const float4*)&Bs[pb][kk][ns];
            #pragma unroll
            for (int i = 0; i < 8; i++)
                #pragma unroll
                for (int j = 0; j < 4; j++)
                    acc[i][j] += af[i] * bf[j];
        }
        As[nb][ac + 0][ar] = av0.x; As[nb][ac + 1][ar] = av0.y;
        As[nb][ac + 2][ar] = av0.z; As[nb][ac + 3][ar] = av0.w;
        As[nb][ac + 4][ar] = av1.x; As[nb][ac + 5][ar] = av1.y;
        As[nb][ac + 6][ar] = av1.z; As[nb][ac + 7][ar] = av1.w;
        *(float4*)&Bs[nb][br][bc] = bv;
        __syncthreads();
    }
    int lb = (kc - 1) & 1;
    #pragma unroll
    for (int kk = 0; kk < 16; kk++) {
        float af[8], bf[4];
        *(float4*)(af)     = *(const float4*)&As[lb][kk][ms];
        *(float4*)(af + 4) = *(const float4*)&As[lb][kk][ms + 4];
        *(float4*)(bf)     = *(const float4*)&Bs[lb][kk][ns];
        #pragma unroll
        for (int i = 0; i < 8; i++)
            #pragma unroll
            for (int j = 0; j < 4; j++)
                acc[i][j] += af[i] * bf[j];
    }
}

// ---------------- fused QKV: grid (36,16); blockIdx.x/12 selects matrix ----------------
__global__ void __launch_bounds__(256, 2) qkv_kernel(
    const float* __restrict__ x,
    const float* __restrict__ Wq, const float* __restrict__ Wk, const float* __restrict__ Wv,
    const float* __restrict__ bq, const float* __restrict__ bk, const float* __restrict__ bv,
    float* __restrict__ q, float* __restrict__ k, float* __restrict__ v)
{
    __shared__ float As[2][16][132];
    __shared__ float Bs[2][16][64];
    int sel = blockIdx.x / 12;
    int bn  = (blockIdx.x % 12) * 64;
    int bm  = blockIdx.y * 128;
    const float* B    = sel == 0 ? Wq : (sel == 1 ? Wk : Wv);
    const float* bias = sel == 0 ? bq : (sel == 1 ? bk : bv);
    float* C          = sel == 0 ? q  : (sel == 1 ? k  : v);
    float acc[8][4] = {};
    gemm_tile(x + (size_t)bm * HID, HID, B + bn, HID, HID, As, Bs, acc);
    int tid = threadIdx.x;
    int ms = (tid >> 4) * 8, ns = (tid & 15) * 4;
    float4 bi = *(const float4*)(bias + bn + ns);
    #pragma unroll
    for (int i = 0; i < 8; i++) {
        float4 o = make_float4(acc[i][0] + bi.x, acc[i][1] + bi.y,
                               acc[i][2] + bi.z, acc[i][3] + bi.w);
        *(float4*)(C + (size_t)(bm + ms + i) * HID + bn + ns) = o;
    }
}

// ---------------- generic gemm: grid (N/64, M/128); mode 0=+bias 2=gelu(+bias) ----------------
__global__ void __launch_bounds__(256, 2) gemm_kernel(
    const float* __restrict__ A, int K,
    const float* __restrict__ B, int N,
    const float* __restrict__ bias,
    float* __restrict__ C, int mode)
{
    __shared__ float As[2][16][132];
    __shared__ float Bs[2][16][64];
    int bm = blockIdx.y * 128, bn = blockIdx.x * 64;
    float acc[8][4] = {};
    gemm_tile(A + (size_t)bm * K, K, B + bn, N, K, As, Bs, acc);
    int tid = threadIdx.x;
    int ms = (tid >> 4) * 8, ns = (tid & 15) * 4;
    float4 bi = *(const float4*)(bias + bn + ns);
    #pragma unroll
    for (int i = 0; i < 8; i++) {
        float o0 = acc[i][0] + bi.x, o1 = acc[i][1] + bi.y;
        float o2 = acc[i][2] + bi.z, o3 = acc[i][3] + bi.w;
        if (mode == 2) { o0 = gelu1(o0); o1 = gelu1(o1); o2 = gelu1(o2); o3 = gelu1(o3); }
        float4 o = make_float4(o0, o1, o2, o3);
        *(float4*)(C + (size_t)(bm + ms + i) * N + bn + ns) = o;
    }
}

// ---------------- split-K=2 gemm: grid (N/64, M/128, 2) -> raw partials ----------------
__global__ void __launch_bounds__(256, 2) gemm_split_kernel(
    const float* __restrict__ A, int K,
    const float* __restrict__ B, int N,
    float* __restrict__ P1, float* __restrict__ P2)
{
    __shared__ float As[2][16][132];
    __shared__ float Bs[2][16][64];
    int bm = blockIdx.y * 128, bn = blockIdx.x * 64;
    int half = K >> 1, z = blockIdx.z;
    float acc[8][4] = {};
    gemm_tile(A + (size_t)bm * K + z * half, K,
              B + (size_t)(z * half) * N + bn, N, half, As, Bs, acc);
    float* C = z ? P2 : P1;
    int tid = threadIdx.x;
    int ms = (tid >> 4) * 8, ns = (tid & 15) * 4;
    #pragma unroll
    for (int i = 0; i < 8; i++) {
        float4 o = make_float4(acc[i][0], acc[i][1], acc[i][2], acc[i][3]);
        *(float4*)(C + (size_t)(bm + ms + i) * N + bn + ns) = o;
    }
}

// ---------------- epilogue: out = p1 + p2 + bias + res ----------------
__global__ void epi_kernel(const float* __restrict__ p1, const float* __restrict__ p2,
                           const float* __restrict__ bias, const float* __restrict__ res,
                           float* __restrict__ out)
{
    int idx = (blockIdx.x * 256 + threadIdx.x) * 4;
    int col = idx % HID;
    float4 a  = *(const float4*)(p1 + idx);
    float4 b  = *(const float4*)(p2 + idx);
    float4 r  = *(const float4*)(res + idx);
    float4 bi = *(const float4*)(bias + col);
    float4 o = make_float4(a.x + b.x + r.x + bi.x, a.y + b.y + r.y + bi.y,
                           a.z + b.z + r.z + bi.z, a.w + b.w + r.w + bi.w);
    *(float4*)(out + idx) = o;
}

// ---------------- L1 distance (f32x2 packed): tile 128(q) x 64(k), 8x4 microtile ----------------
__global__ void __launch_bounds__(256) dist_kernel(
    const float* __restrict__ Q, const float* __restrict__ Km,
    const float* __restrict__ lamp, float* __restrict__ attn)
{
    __shared__ unsigned long long Qs[32][128];   // [d-pair][q-row]
    __shared__ unsigned long long Ks[32][64];    // negated K
    int bh = blockIdx.z, b = bh / NHEAD, h = bh - b * NHEAD;
    int qbase = blockIdx.y * 128, kbase = blockIdx.x * 64;
    const float* Qb = Q  + (size_t)b * SEQ * HID + h * HDIM + (size_t)qbase * HID;
    const float* Kb = Km + (size_t)b * SEQ * HID + h * HDIM + (size_t)kbase * HID;
    int tid = threadIdx.x;

    union F2U { float2 f; unsigned long long u; };
    {   // Q: 128 rows, each thread loads 32 dims of one row
        int row = tid >> 1, hh = (tid & 1) * 32;
        #pragma unroll
        for (int i = 0; i < 8; i++) {
            float4 qv = *(const float4*)(Qb + (size_t)row * HID + hh + i * 4);
            F2U t;
            t.f = make_float2(qv.x, qv.y); Qs[(hh >> 1) + i * 2][row]     = t.u;
            t.f = make_float2(qv.z, qv.w); Qs[(hh >> 1) + i * 2 + 1][row] = t.u;
        }
    }
    {   // K: 64 rows, each thread loads 16 dims of one row (negated)
        int row = tid >> 2, kq = (tid & 3) * 16;
        #pragma unroll
        for (int i = 0; i < 4; i++) {
            float4 kv = *(const float4*)(Kb + (size_t)row * HID + kq + i * 4);
            F2U t;
            t.f = make_float2(-kv.x, -kv.y); Ks[(kq >> 1) + i * 2][row]     = t.u;
            t.f = make_float2(-kv.z, -kv.w); Ks[(kq >> 1) + i * 2 + 1][row] = t.u;
        }
    }
    __syncthreads();

    int tx = tid & 15, ty = tid >> 4;
    int qs = ty * 8, ks = tx * 4;
    unsigned long long acc[8][4] = {};
    const unsigned long long MASK = 0x7FFFFFFF7FFFFFFFull;
    #pragma unroll 4
    for (int d = 0; d < 32; d++) {
        unsigned long long qv[8], kv[4];
        *(ulonglong2*)&qv[0] = *(const ulonglong2*)&Qs[d][qs];
        *(ulonglong2*)&qv[2] = *(const ulonglong2*)&Qs[d][qs + 2];
        *(ulonglong2*)&qv[4] = *(const ulonglong2*)&Qs[d][qs + 4];
        *(ulonglong2*)&qv[6] = *(const ulonglong2*)&Qs[d][qs + 6];
        *(ulonglong2*)&kv[0] = *(const ulonglong2*)&Ks[d][ks];
        *(ulonglong2*)&kv[2] = *(const ulonglong2*)&Ks[d][ks + 2];
        #pragma unroll
        for (int i = 0; i < 8; i++)
            #pragma unroll
            for (int j = 0; j < 4; j++) {
                unsigned long long df = f2add(qv[i], kv[j]) & MASK;
                acc[i][j] = f2add(acc[i][j], df);
            }
    }
    float c = -(*lamp) * 0.125f;   // scale = 1/sqrt(64)
    float* outp = attn + (size_t)bh * SEQ * SEQ + (size_t)(qbase + qs) * SEQ + kbase + ks;
    #pragma unroll
    for (int i = 0; i < 8; i++) {
        float4 o;
        F2U t;
        t.u = acc[i][0]; o.x = c * (t.f.x + t.f.y);
        t.u = acc[i][1]; o.y = c * (t.f.x + t.f.y);
        t.u = acc[i][2]; o.z = c * (t.f.x + t.f.y);
        t.u = acc[i][3]; o.w = c * (t.f.x + t.f.y);
        *(float4*)(outp + (size_t)i * SEQ) = o;
    }
}

// ---------------- row softmax in place (rows of 1024) ----------------
__global__ void softmax_kernel(float* __restrict__ attn) {
    size_t row = blockIdx.x;
    float* p = attn + row * SEQ;
    int t = threadIdx.x;
    float4 v = *(float4*)(p + t * 4);
    __shared__ float sh[8];
    float mx = fmaxf(fmaxf(v.x, v.y), fmaxf(v.z, v.w));
    #pragma unroll
    for (int o = 16; o; o >>= 1) mx = fmaxf(mx, __shfl_xor_sync(0xffffffffu, mx, o));
    if (!(t & 31)) sh[t >> 5] = mx;
    __syncthreads();
    float m = sh[0];
    #pragma unroll
    for (int i = 1; i < 8; i++) m = fmaxf(m, sh[i]);
    __syncthreads();
    float4 e;
    e.x = expf(v.x - m); e.y = expf(v.y - m);
    e.z = expf(v.z - m); e.w = expf(v.w - m);
    float s = e.x + e.y + e.z + e.w;
    #pragma unroll
    for (int o = 16; o; o >>= 1) s += __shfl_xor_sync(0xffffffffu, s, o);
    if (!(t & 31)) sh[t >> 5] = s;
    __syncthreads();
    float tot = 0.f;
    #pragma unroll
    for (int i = 0; i < 8; i++) tot += sh[i];
    float inv = 1.f / tot;
    e.x *= inv; e.y *= inv; e.z *= inv; e.w *= inv;
    *(float4*)(p + t * 4) = e;
}

// ---------------- out = attn @ V per head: grid (8,1,24), 128x64 engine ----------------
__global__ void __launch_bounds__(256, 2) pv_kernel(
    const float* __restrict__ attn, const float* __restrict__ V, float* __restrict__ O)
{
    __shared__ float As[2][16][132];
    __shared__ float Bs[2][16][64];
    int bh = blockIdx.z, b = bh / NHEAD, h = bh - b * NHEAD;
    int bm = blockIdx.x * 128;
    const float* A  = attn + (size_t)bh * SEQ * SEQ + (size_t)bm * SEQ;
    const float* Bv = V + (size_t)b * SEQ * HID + h * HDIM;
    float acc[8][4] = {};
    gemm_tile(A, SEQ, Bv, HID, SEQ, As, Bs, acc);
    float* Ob = O + (size_t)b * SEQ * HID + h * HDIM + (size_t)bm * HID;
    int tid = threadIdx.x;
    int ms = (tid >> 4) * 8, ns = (tid & 15) * 4;
    #pragma unroll
    for (int i = 0; i < 8; i++) {
        float4 o = make_float4(acc[i][0], acc[i][1], acc[i][2], acc[i][3]);
        *(float4*)(Ob + (size_t)(ms + i) * HID + ns) = o;
    }
}

// ---------------- launch ----------------
extern "C" void kernel_launch(void* const* d_in, const int* in_sizes, int n_in,
                              void* d_out, int out_size) {
    const float* hidden = (const float*)d_in[0];
    const float* ln1g = (const float*)d_in[1];
    const float* ln1b = (const float*)d_in[2];
    const float* Wq = (const float*)d_in[3];
    const float* bq = (const float*)d_in[4];
    const float* Wk = (const float*)d_in[5];
    const float* bk = (const float*)d_in[6];
    const float* Wv = (const float*)d_in[7];
    const float* bv = (const float*)d_in[8];
    const float* Wo = (const float*)d_in[9];
    const float* bo = (const float*)d_in[10];
    const float* lam = (const float*)d_in[11];
    const float* ln2g = (const float*)d_in[12];
    const float* ln2b = (const float*)d_in[13];
    const float* W1 = (const float*)d_in[14];
    const float* b1 = (const float*)d_in[15];
    const float* W2 = (const float*)d_in[16];
    const float* b2 = (const float*)d_in[17];

    float* out0 = (float*)d_out;
    float* attn = out0 + (size_t)MTOT * HID;  // [B,NH,S,S] follows [B,S,H]

    float *x, *q, *k, *v, *ao, *r1, *y, *ff;
    cudaGetSymbolAddress((void**)&x,  g_x);
    cudaGetSymbolAddress((void**)&q,  g_q);
    cudaGetSymbolAddress((void**)&k,  g_k);
    cudaGetSymbolAddress((void**)&v,  g_v);
    cudaGetSymbolAddress((void**)&ao, g_ao);
    cudaGetSymbolAddress((void**)&r1, g_r1);
    cudaGetSymbolAddress((void**)&y,  g_y);
    cudaGetSymbolAddress((void**)&ff, g_ff);

    int epiGrid = (MTOT * HID) / (256 * 4);   // 1536

    ln_kernel<<<MTOT, 256>>>(hidden, ln1g, ln1b, x);
    qkv_kernel<<<dim3(36, 16), 256>>>(x, Wq, Wk, Wv, bq, bk, bv, q, k, v);
    dist_kernel<<<dim3(SEQ / 64, SEQ / 128, BHTOT), 256>>>(q, k, lam, attn);
    softmax_kernel<<<BHTOT * SEQ, 256>>>(attn);
    pv_kernel<<<dim3(SEQ / 128, 1, BHTOT), 256>>>(attn, v, ao);
    // Wo with split-K=2: partials in g_x (x free) and g_ff (free until FF1)
    gemm_split_kernel<<<dim3(12, 16, 2), 256>>>(ao, HID, Wo, HID, x, ff);
    epi_kernel<<<epiGrid, 256>>>(x, ff, bo, hidden, r1);
    ln_kernel<<<MTOT, 256>>>(r1, ln2g, ln2b, y);
    gemm_kernel<<<dim3(48, 16), 256>>>(y, HID, W1, FFD, b1, ff, 2);          // gelu (N=3072 -> 48 blocks)
    // FF2 with split-K=2: partials in g_x and g_q (both free now)
    gemm_split_kernel<<<dim3(12, 16, 2), 256>>>(ff, FFD, W2, HID, x, q);
    epi_kernel<<<epiGrid, 256>>>(x, q, b2, r1, out0);
}

// round 8
// speedup vs baseline: 2.5974x; 1.5344x over previous
#include <cuda_runtime.h>
#include <math.h>
#include <stdint.h>

#define SEQ   1024
#define BATCH 2
#define HID   768
#define NHEAD 12
#define HDIM  64
#define FFD   3072
#define MTOT  (BATCH*SEQ)   // 2048
#define BHTOT (BATCH*NHEAD) // 24

#define APAD 136
#define BPAD 72

// ---------------- scratch (device globals: no allocation allowed) ----------------
__device__ float g_x [MTOT*HID];
__device__ float g_q [MTOT*HID];
__device__ float g_k [MTOT*HID];
__device__ float g_v [MTOT*HID];
__device__ float g_ao[MTOT*HID];
__device__ float g_r1[MTOT*HID];
__device__ float g_y [MTOT*HID];
__device__ float g_ff[MTOT*FFD];

// ---------------- helpers ----------------
__device__ __forceinline__ unsigned long long f2add(unsigned long long a, unsigned long long b) {
    unsigned long long r;
    asm("add.rn.f32x2 %0, %1, %2;" : "=l"(r) : "l"(a), "l"(b));
    return r;
}

__device__ __forceinline__ float gelu1(float v) {
    return 0.5f * v * (1.f + erff(v * 0.70710678118654752f));
}

__device__ __forceinline__ float to_tf32(float x) {
    uint32_t u;
    asm("cvt.rna.tf32.f32 %0, %1;" : "=r"(u) : "f"(x));
    return __uint_as_float(u);
}

__device__ __forceinline__ void mma_tf32(float (&c)[4], const uint32_t (&a)[4],
                                         uint32_t b0, uint32_t b1) {
    asm("mma.sync.aligned.m16n8k8.row.col.f32.tf32.tf32.f32 "
        "{%0,%1,%2,%3}, {%4,%5,%6,%7}, {%8,%9}, {%0,%1,%2,%3};"
        : "+f"(c[0]), "+f"(c[1]), "+f"(c[2]), "+f"(c[3])
        : "r"(a[0]), "r"(a[1]), "r"(a[2]), "r"(a[3]), "r"(b0), "r"(b1));
}

// ---------------- LayerNorm: one block per row of 768 ----------------
__global__ void ln_kernel(const float* __restrict__ in, const float* __restrict__ g,
                          const float* __restrict__ b, float* __restrict__ out) {
    int row = blockIdx.x;
    const float* x = in + (size_t)row * HID;
    int t = threadIdx.x;
    float v0 = x[t], v1 = x[t + 256], v2 = x[t + 512];
    float s  = v0 + v1 + v2;
    float sq = v0 * v0 + v1 * v1 + v2 * v2;
    __shared__ float sh[16];
    #pragma unroll
    for (int o = 16; o; o >>= 1) {
        s  += __shfl_xor_sync(0xffffffffu, s,  o);
        sq += __shfl_xor_sync(0xffffffffu, sq, o);
    }
    int w = t >> 5, l = t & 31;
    if (!l) { sh[w] = s; sh[w + 8] = sq; }
    __syncthreads();
    if (w == 0) {
        float a = (l < 8) ? sh[l] : 0.f;
        float c = (l < 8) ? sh[l + 8] : 0.f;
        #pragma unroll
        for (int o = 4; o; o >>= 1) {
            a += __shfl_xor_sync(0xffffffffu, a, o);
            c += __shfl_xor_sync(0xffffffffu, c, o);
        }
        if (!l) { sh[0] = a; sh[1] = c; }
    }
    __syncthreads();
    float mean = sh[0] * (1.f / HID);
    float var  = sh[1] * (1.f / HID) - mean * mean;
    float rs   = rsqrtf(var + 1e-5f);
    float* o = out + (size_t)row * HID;
    o[t]       = (v0 - mean) * rs * g[t]       + b[t];
    o[t + 256] = (v1 - mean) * rs * g[t + 256] + b[t + 256];
    o[t + 512] = (v2 - mean) * rs * g[t + 512] + b[t + 512];
}

// ---------------- tf32 MMA compute on one smem buffer ----------------
__device__ __forceinline__ void mma_compute(
    const float (*Ab)[APAD], const float (*Bb)[BPAD],
    int m_base, int n_base, int gid, int tig, float (&acc)[2][4][4])
{
    #pragma unroll
    for (int ks = 0; ks < 16; ks += 8) {
        uint32_t a[2][4];
        #pragma unroll
        for (int mf = 0; mf < 2; mf++) {
            int m0 = m_base + mf * 16 + gid;
            a[mf][0] = __float_as_uint(Ab[ks + tig][m0]);
            a[mf][1] = __float_as_uint(Ab[ks + tig][m0 + 8]);
            a[mf][2] = __float_as_uint(Ab[ks + tig + 4][m0]);
            a[mf][3] = __float_as_uint(Ab[ks + tig + 4][m0 + 8]);
        }
        #pragma unroll
        for (int nf = 0; nf < 4; nf++) {
            int n0 = n_base + nf * 8 + gid;
            uint32_t b0 = __float_as_uint(Bb[ks + tig][n0]);
            uint32_t b1 = __float_as_uint(Bb[ks + tig + 4][n0]);
            mma_tf32(acc[0][nf], a[0], b0, b1);
            mma_tf32(acc[1][nf], a[1], b0, b1);
        }
    }
}

// ---------------- core: 128x64 tile, BK=16, double-buffered, tf32 tensor ----------------
// kLen must be a multiple of 16 and >= 32.
__device__ __forceinline__ void mma_tile(
    const float* __restrict__ A, int lda,
    const float* __restrict__ B, int ldb,
    int kLen,
    float (*As)[16][APAD], float (*Bs)[16][BPAD],
    float (&acc)[2][4][4])
{
    int tid = threadIdx.x;
    int ar = tid >> 1, ac = (tid & 1) * 8;
    int br = tid >> 4, bc = (tid & 15) * 4;
    int lane = tid & 31, wid = tid >> 5;
    int gid = lane >> 2, tig = lane & 3;
    int m_base = (wid & 3) * 32, n_base = (wid >> 2) * 32;

    const float* Ap = A + (size_t)ar * lda + ac;
    const float* Bp = B + (size_t)br * ldb + bc;

    {   // prefetch chunk 0 -> smem buf 0 (with tf32 rounding)
        float4 av0 = *(const float4*)(Ap);
        float4 av1 = *(const float4*)(Ap + 4);
        float4 bv  = *(const float4*)(Bp);
        As[0][ac + 0][ar] = to_tf32(av0.x); As[0][ac + 1][ar] = to_tf32(av0.y);
        As[0][ac + 2][ar] = to_tf32(av0.z); As[0][ac + 3][ar] = to_tf32(av0.w);
        As[0][ac + 4][ar] = to_tf32(av1.x); As[0][ac + 5][ar] = to_tf32(av1.y);
        As[0][ac + 6][ar] = to_tf32(av1.z); As[0][ac + 7][ar] = to_tf32(av1.w);
        float4 bt = make_float4(to_tf32(bv.x), to_tf32(bv.y), to_tf32(bv.z), to_tf32(bv.w));
        *(float4*)&Bs[0][br][bc] = bt;
    }
    __syncthreads();

    int kc = kLen >> 4;
    for (int c = 1; c < kc; c++) {
        const float* Ac = Ap + c * 16;
        float4 av0 = *(const float4*)(Ac);
        float4 av1 = *(const float4*)(Ac + 4);
        float4 bv  = *(const float4*)(Bp + (size_t)(c * 16) * ldb);
        int pb = (c - 1) & 1, nb = c & 1;
        mma_compute(As[pb], Bs[pb], m_base, n_base, gid, tig, acc);
        As[nb][ac + 0][ar] = to_tf32(av0.x); As[nb][ac + 1][ar] = to_tf32(av0.y);
        As[nb][ac + 2][ar] = to_tf32(av0.z); As[nb][ac + 3][ar] = to_tf32(av0.w);
        As[nb][ac + 4][ar] = to_tf32(av1.x); As[nb][ac + 5][ar] = to_tf32(av1.y);
        As[nb][ac + 6][ar] = to_tf32(av1.z); As[nb][ac + 7][ar] = to_tf32(av1.w);
        float4 bt = make_float4(to_tf32(bv.x), to_tf32(bv.y), to_tf32(bv.z), to_tf32(bv.w));
        *(float4*)&Bs[nb][br][bc] = bt;
        __syncthreads();
    }
    int lb = (kc - 1) & 1;
    mma_compute(As[lb], Bs[lb], m_base, n_base, gid, tig, acc);
}

// ---------------- fused QKV: grid (36,16); blockIdx.x/12 selects matrix ----------------
__global__ void __launch_bounds__(256, 2) qkv_kernel(
    const float* __restrict__ x,
    const float* __restrict__ Wq, const float* __restrict__ Wk, const float* __restrict__ Wv,
    const float* __restrict__ bq, const float* __restrict__ bk, const float* __restrict__ bv,
    float* __restrict__ q, float* __restrict__ k, float* __restrict__ v)
{
    __shared__ float As[2][16][APAD];
    __shared__ float Bs[2][16][BPAD];
    int sel = blockIdx.x / 12;
    int bn  = (blockIdx.x % 12) * 64;
    int bm  = blockIdx.y * 128;
    const float* B    = sel == 0 ? Wq : (sel == 1 ? Wk : Wv);
    const float* bias = sel == 0 ? bq : (sel == 1 ? bk : bv);
    float* C          = sel == 0 ? q  : (sel == 1 ? k  : v);
    float acc[2][4][4] = {};
    mma_tile(x + (size_t)bm * HID, HID, B + bn, HID, HID, As, Bs, acc);
    int tid = threadIdx.x, lane = tid & 31, wid = tid >> 5;
    int gid = lane >> 2, tig = lane & 3;
    int m_base = (wid & 3) * 32, n_base = (wid >> 2) * 32;
    #pragma unroll
    for (int mf = 0; mf < 2; mf++) {
        int r0 = bm + m_base + mf * 16 + gid;
        #pragma unroll
        for (int nf = 0; nf < 4; nf++) {
            int col = bn + n_base + nf * 8 + tig * 2;
            float2 bi = *(const float2*)(bias + col);
            *(float2*)(C + (size_t)r0 * HID + col) =
                make_float2(acc[mf][nf][0] + bi.x, acc[mf][nf][1] + bi.y);
            *(float2*)(C + (size_t)(r0 + 8) * HID + col) =
                make_float2(acc[mf][nf][2] + bi.x, acc[mf][nf][3] + bi.y);
        }
    }
}

// ---------------- generic gemm: grid (N/64, M/128); mode 0=+bias 2=gelu(+bias) ----------------
__global__ void __launch_bounds__(256, 2) gemm_kernel(
    const float* __restrict__ A, int K,
    const float* __restrict__ B, int N,
    const float* __restrict__ bias,
    float* __restrict__ C, int mode)
{
    __shared__ float As[2][16][APAD];
    __shared__ float Bs[2][16][BPAD];
    int bm = blockIdx.y * 128, bn = blockIdx.x * 64;
    float acc[2][4][4] = {};
    mma_tile(A + (size_t)bm * K, K, B + bn, N, K, As, Bs, acc);
    int tid = threadIdx.x, lane = tid & 31, wid = tid >> 5;
    int gid = lane >> 2, tig = lane & 3;
    int m_base = (wid & 3) * 32, n_base = (wid >> 2) * 32;
    #pragma unroll
    for (int mf = 0; mf < 2; mf++) {
        int r0 = bm + m_base + mf * 16 + gid;
        #pragma unroll
        for (int nf = 0; nf < 4; nf++) {
            int col = bn + n_base + nf * 8 + tig * 2;
            float2 bi = *(const float2*)(bias + col);
            float o0 = acc[mf][nf][0] + bi.x, o1 = acc[mf][nf][1] + bi.y;
            float o2 = acc[mf][nf][2] + bi.x, o3 = acc[mf][nf][3] + bi.y;
            if (mode == 2) { o0 = gelu1(o0); o1 = gelu1(o1); o2 = gelu1(o2); o3 = gelu1(o3); }
            *(float2*)(C + (size_t)r0 * N + col)       = make_float2(o0, o1);
            *(float2*)(C + (size_t)(r0 + 8) * N + col) = make_float2(o2, o3);
        }
    }
}

// ---------------- split-K=2 gemm: grid (N/64, M/128, 2) -> raw partials ----------------
__global__ void __launch_bounds__(256, 2) gemm_split_kernel(
    const float* __restrict__ A, int K,
    const float* __restrict__ B, int N,
    float* __restrict__ P1, float* __restrict__ P2)
{
    __shared__ float As[2][16][APAD];
    __shared__ float Bs[2][16][BPAD];
    int bm = blockIdx.y * 128, bn = blockIdx.x * 64;
    int half = K >> 1, z = blockIdx.z;
    float acc[2][4][4] = {};
    mma_tile(A + (size_t)bm * K + z * half, K,
             B + (size_t)(z * half) * N + bn, N, half, As, Bs, acc);
    float* C = z ? P2 : P1;
    int tid = threadIdx.x, lane = tid & 31, wid = tid >> 5;
    int gid = lane >> 2, tig = lane & 3;
    int m_base = (wid & 3) * 32, n_base = (wid >> 2) * 32;
    #pragma unroll
    for (int mf = 0; mf < 2; mf++) {
        int r0 = bm + m_base + mf * 16 + gid;
        #pragma unroll
        for (int nf = 0; nf < 4; nf++) {
            int col = bn + n_base + nf * 8 + tig * 2;
            *(float2*)(C + (size_t)r0 * N + col)       = make_float2(acc[mf][nf][0], acc[mf][nf][1]);
            *(float2*)(C + (size_t)(r0 + 8) * N + col) = make_float2(acc[mf][nf][2], acc[mf][nf][3]);
        }
    }
}

// ---------------- epilogue: out = p1 + p2 + bias + res ----------------
__global__ void epi_kernel(const float* __restrict__ p1, const float* __restrict__ p2,
                           const float* __restrict__ bias, const float* __restrict__ res,
                           float* __restrict__ out)
{
    int idx = (blockIdx.x * 256 + threadIdx.x) * 4;
    int col = idx % HID;
    float4 a  = *(const float4*)(p1 + idx);
    float4 b  = *(const float4*)(p2 + idx);
    float4 r  = *(const float4*)(res + idx);
    float4 bi = *(const float4*)(bias + col);
    float4 o = make_float4(a.x + b.x + r.x + bi.x, a.y + b.y + r.y + bi.y,
                           a.z + b.z + r.z + bi.z, a.w + b.w + r.w + bi.w);
    *(float4*)(out + idx) = o;
}

// ---------------- L1 distance (f32x2 packed): tile 128(q) x 64(k), 8x4 microtile ----------------
__global__ void __launch_bounds__(256) dist_kernel(
    const float* __restrict__ Q, const float* __restrict__ Km,
    const float* __restrict__ lamp, float* __restrict__ attn)
{
    __shared__ unsigned long long Qs[32][128];   // [d-pair][q-row]
    __shared__ unsigned long long Ks[32][64];    // negated K
    int bh = blockIdx.z, b = bh / NHEAD, h = bh - b * NHEAD;
    int qbase = blockIdx.y * 128, kbase = blockIdx.x * 64;
    const float* Qb = Q  + (size_t)b * SEQ * HID + h * HDIM + (size_t)qbase * HID;
    const float* Kb = Km + (size_t)b * SEQ * HID + h * HDIM + (size_t)kbase * HID;
    int tid = threadIdx.x;

    union F2U { float2 f; unsigned long long u; };
    {   // Q: 128 rows, each thread loads 32 dims of one row
        int row = tid >> 1, hh = (tid & 1) * 32;
        #pragma unroll
        for (int i = 0; i < 8; i++) {
            float4 qv = *(const float4*)(Qb + (size_t)row * HID + hh + i * 4);
            F2U t;
            t.f = make_float2(qv.x, qv.y); Qs[(hh >> 1) + i * 2][row]     = t.u;
            t.f = make_float2(qv.z, qv.w); Qs[(hh >> 1) + i * 2 + 1][row] = t.u;
        }
    }
    {   // K: 64 rows, each thread loads 16 dims of one row (negated)
        int row = tid >> 2, kq = (tid & 3) * 16;
        #pragma unroll
        for (int i = 0; i < 4; i++) {
            float4 kv = *(const float4*)(Kb + (size_t)row * HID + kq + i * 4);
            F2U t;
            t.f = make_float2(-kv.x, -kv.y); Ks[(kq >> 1) + i * 2][row]     = t.u;
            t.f = make_float2(-kv.z, -kv.w); Ks[(kq >> 1) + i * 2 + 1][row] = t.u;
        }
    }
    __syncthreads();

    int tx = tid & 15, ty = tid >> 4;
    int qs = ty * 8, ks = tx * 4;
    unsigned long long acc[8][4] = {};
    const unsigned long long MASK = 0x7FFFFFFF7FFFFFFFull;
    #pragma unroll 4
    for (int d = 0; d < 32; d++) {
        unsigned long long qv[8], kv[4];
        *(ulonglong2*)&qv[0] = *(const ulonglong2*)&Qs[d][qs];
        *(ulonglong2*)&qv[2] = *(const ulonglong2*)&Qs[d][qs + 2];
        *(ulonglong2*)&qv[4] = *(const ulonglong2*)&Qs[d][qs + 4];
        *(ulonglong2*)&qv[6] = *(const ulonglong2*)&Qs[d][qs + 6];
        *(ulonglong2*)&kv[0] = *(const ulonglong2*)&Ks[d][ks];
        *(ulonglong2*)&kv[2] = *(const ulonglong2*)&Ks[d][ks + 2];
        #pragma unroll
        for (int i = 0; i < 8; i++)
            #pragma unroll
            for (int j = 0; j < 4; j++) {
                unsigned long long df = f2add(qv[i], kv[j]) & MASK;
                acc[i][j] = f2add(acc[i][j], df);
            }
    }
    float c = -(*lamp) * 0.125f;   // scale = 1/sqrt(64)
    float* outp = attn + (size_t)bh * SEQ * SEQ + (size_t)(qbase + qs) * SEQ + kbase + ks;
    #pragma unroll
    for (int i = 0; i < 8; i++) {
        float4 o;
        F2U t;
        t.u = acc[i][0]; o.x = c * (t.f.x + t.f.y);
        t.u = acc[i][1]; o.y = c * (t.f.x + t.f.y);
        t.u = acc[i][2]; o.z = c * (t.f.x + t.f.y);
        t.u = acc[i][3]; o.w = c * (t.f.x + t.f.y);
        *(float4*)(outp + (size_t)i * SEQ) = o;
    }
}

// ---------------- row softmax in place (rows of 1024) ----------------
__global__ void softmax_kernel(float* __restrict__ attn) {
    size_t row = blockIdx.x;
    float* p = attn + row * SEQ;
    int t = threadIdx.x;
    float4 v = *(float4*)(p + t * 4);
    __shared__ float sh[8];
    float mx = fmaxf(fmaxf(v.x, v.y), fmaxf(v.z, v.w));
    #pragma unroll
    for (int o = 16; o; o >>= 1) mx = fmaxf(mx, __shfl_xor_sync(0xffffffffu, mx, o));
    if (!(t & 31)) sh[t >> 5] = mx;
    __syncthreads();
    float m = sh[0];
    #pragma unroll
    for (int i = 1; i < 8; i++) m = fmaxf(m, sh[i]);
    __syncthreads();
    float4 e;
    e.x = expf(v.x - m); e.y = expf(v.y - m);
    e.z = expf(v.z - m); e.w = expf(v.w - m);
    float s = e.x + e.y + e.z + e.w;
    #pragma unroll
    for (int o = 16; o; o >>= 1) s += __shfl_xor_sync(0xffffffffu, s, o);
    if (!(t & 31)) sh[t >> 5] = s;
    __syncthreads();
    float tot = 0.f;
    #pragma unroll
    for (int i = 0; i < 8; i++) tot += sh[i];
    float inv = 1.f / tot;
    e.x *= inv; e.y *= inv; e.z *= inv; e.w *= inv;
    *(float4*)(p + t * 4) = e;
}

// ---------------- out = attn @ V per head: grid (8,1,24), 128x64 tf32 engine ----------------
__global__ void __launch_bounds__(256, 2) pv_kernel(
    const float* __restrict__ attn, const float* __restrict__ V, float* __restrict__ O)
{
    __shared__ float As[2][16][APAD];
    __shared__ float Bs[2][16][BPAD];
    int bh = blockIdx.z, b = bh / NHEAD, h = bh - b * NHEAD;
    int bm = blockIdx.x * 128;
    const float* A  = attn + (size_t)bh * SEQ * SEQ + (size_t)bm * SEQ;
    const float* Bv = V + (size_t)b * SEQ * HID + h * HDIM;
    float acc[2][4][4] = {};
    mma_tile(A, SEQ, Bv, HID, SEQ, As, Bs, acc);
    float* Ob = O + (size_t)b * SEQ * HID + h * HDIM + (size_t)bm * HID;
    int tid = threadIdx.x, lane = tid & 31, wid = tid >> 5;
    int gid = lane >> 2, tig = lane & 3;
    int m_base = (wid & 3) * 32, n_base = (wid >> 2) * 32;
    #pragma unroll
    for (int mf = 0; mf < 2; mf++) {
        int r0 = m_base + mf * 16 + gid;
        #pragma unroll
        for (int nf = 0; nf < 4; nf++) {
            int col = n_base + nf * 8 + tig * 2;
            *(float2*)(Ob + (size_t)r0 * HID + col)       = make_float2(acc[mf][nf][0], acc[mf][nf][1]);
            *(float2*)(Ob + (size_t)(r0 + 8) * HID + col) = make_float2(acc[mf][nf][2], acc[mf][nf][3]);
        }
    }
}

// ---------------- launch ----------------
extern "C" void kernel_launch(void* const* d_in, const int* in_sizes, int n_in,
                              void* d_out, int out_size) {
    const float* hidden = (const float*)d_in[0];
    const float* ln1g = (const float*)d_in[1];
    const float* ln1b = (const float*)d_in[2];
    const float* Wq = (const float*)d_in[3];
    const float* bq = (const float*)d_in[4];
    const float* Wk = (const float*)d_in[5];
    const float* bk = (const float*)d_in[6];
    const float* Wv = (const float*)d_in[7];
    const float* bv = (const float*)d_in[8];
    const float* Wo = (const float*)d_in[9];
    const float* bo = (const float*)d_in[10];
    const float* lam = (const float*)d_in[11];
    const float* ln2g = (const float*)d_in[12];
    const float* ln2b = (const float*)d_in[13];
    const float* W1 = (const float*)d_in[14];
    const float* b1 = (const float*)d_in[15];
    const float* W2 = (const float*)d_in[16];
    const float* b2 = (const float*)d_in[17];

    float* out0 = (float*)d_out;
    float* attn = out0 + (size_t)MTOT * HID;  // [B,NH,S,S] follows [B,S,H]

    float *x, *q, *k, *v, *ao, *r1, *y, *ff;
    cudaGetSymbolAddress((void**)&x,  g_x);
    cudaGetSymbolAddress((void**)&q,  g_q);
    cudaGetSymbolAddress((void**)&k,  g_k);
    cudaGetSymbolAddress((void**)&v,  g_v);
    cudaGetSymbolAddress((void**)&ao, g_ao);
    cudaGetSymbolAddress((void**)&r1, g_r1);
    cudaGetSymbolAddress((void**)&y,  g_y);
    cudaGetSymbolAddress((void**)&ff, g_ff);

    int epiGrid = (MTOT * HID) / (256 * 4);   // 1536

    ln_kernel<<<MTOT, 256>>>(hidden, ln1g, ln1b, x);
    qkv_kernel<<<dim3(36, 16), 256>>>(x, Wq, Wk, Wv, bq, bk, bv, q, k, v);
    dist_kernel<<<dim3(SEQ / 64, SEQ / 128, BHTOT), 256>>>(q, k, lam, attn);
    softmax_kernel<<<BHTOT * SEQ, 256>>>(attn);
    pv_kernel<<<dim3(SEQ / 128, 1, BHTOT), 256>>>(attn, v, ao);
    // Wo with split-K=2: partials in g_x (x free) and g_ff (free until FF1)
    gemm_split_kernel<<<dim3(12, 16, 2), 256>>>(ao, HID, Wo, HID, x, ff);
    epi_kernel<<<epiGrid, 256>>>(x, ff, bo, hidden, r1);
    ln_kernel<<<MTOT, 256>>>(r1, ln2g, ln2b, y);
    gemm_kernel<<<dim3(48, 16), 256>>>(y, HID, W1, FFD, b1, ff, 2);          // gelu (N=3072)
    // FF2 with split-K=2: partials in g_x and g_q (both free now)
    gemm_split_kernel<<<dim3(12, 16, 2), 256>>>(ff, FFD, W2, HID, x, q);
    epi_kernel<<<epiGrid, 256>>>(x, q, b2, r1, out0);
}

// round 9
// speedup vs baseline: 2.9503x; 1.1359x over previous
#include <cuda_runtime.h>
#include <math.h>
#include <stdint.h>

#define SEQ   1024
#define BATCH 2
#define HID   768
#define NHEAD 12
#define HDIM  64
#define FFD   3072
#define MTOT  (BATCH*SEQ)   // 2048
#define BHTOT (BATCH*NHEAD) // 24

#define APAD 136
#define BPAD 72
#define BPAD2 136

// ---------------- scratch (device globals: no allocation allowed) ----------------
__device__ float g_x [MTOT*HID];
__device__ float g_q [MTOT*HID];
__device__ float g_k [MTOT*HID];
__device__ float g_v [MTOT*HID];
__device__ float g_ao[MTOT*HID];
__device__ float g_r1[MTOT*HID];
__device__ float g_y [MTOT*HID];
__device__ float g_ff[MTOT*FFD];

// ---------------- helpers ----------------
__device__ __forceinline__ unsigned long long f2add(unsigned long long a, unsigned long long b) {
    unsigned long long r;
    asm("add.rn.f32x2 %0, %1, %2;" : "=l"(r) : "l"(a), "l"(b));
    return r;
}

__device__ __forceinline__ float gelu1(float v) {
    return 0.5f * v * (1.f + erff(v * 0.70710678118654752f));
}

__device__ __forceinline__ float to_tf32(float x) {
    uint32_t u;
    asm("cvt.rna.tf32.f32 %0, %1;" : "=r"(u) : "f"(x));
    return __uint_as_float(u);
}

__device__ __forceinline__ void mma_tf32(float (&c)[4], const uint32_t (&a)[4],
                                         uint32_t b0, uint32_t b1) {
    asm("mma.sync.aligned.m16n8k8.row.col.f32.tf32.tf32.f32 "
        "{%0,%1,%2,%3}, {%4,%5,%6,%7}, {%8,%9}, {%0,%1,%2,%3};"
        : "+f"(c[0]), "+f"(c[1]), "+f"(c[2]), "+f"(c[3])
        : "r"(a[0]), "r"(a[1]), "r"(a[2]), "r"(a[3]), "r"(b0), "r"(b1));
}

// ---------------- LayerNorm: one block per row of 768 ----------------
__global__ void ln_kernel(const float* __restrict__ in, const float* __restrict__ g,
                          const float* __restrict__ b, float* __restrict__ out) {
    int row = blockIdx.x;
    const float* x = in + (size_t)row * HID;
    int t = threadIdx.x;
    float v0 = x[t], v1 = x[t + 256], v2 = x[t + 512];
    float s  = v0 + v1 + v2;
    float sq = v0 * v0 + v1 * v1 + v2 * v2;
    __shared__ float sh[16];
    #pragma unroll
    for (int o = 16; o; o >>= 1) {
        s  += __shfl_xor_sync(0xffffffffu, s,  o);
        sq += __shfl_xor_sync(0xffffffffu, sq, o);
    }
    int w = t >> 5, l = t & 31;
    if (!l) { sh[w] = s; sh[w + 8] = sq; }
    __syncthreads();
    if (w == 0) {
        float a = (l < 8) ? sh[l] : 0.f;
        float c = (l < 8) ? sh[l + 8] : 0.f;
        #pragma unroll
        for (int o = 4; o; o >>= 1) {
            a += __shfl_xor_sync(0xffffffffu, a, o);
            c += __shfl_xor_sync(0xffffffffu, c, o);
        }
        if (!l) { sh[0] = a; sh[1] = c; }
    }
    __syncthreads();
    float mean = sh[0] * (1.f / HID);
    float var  = sh[1] * (1.f / HID) - mean * mean;
    float rs   = rsqrtf(var + 1e-5f);
    float* o = out + (size_t)row * HID;
    o[t]       = (v0 - mean) * rs * g[t]       + b[t];
    o[t + 256] = (v1 - mean) * rs * g[t + 256] + b[t + 256];
    o[t + 512] = (v2 - mean) * rs * g[t + 512] + b[t + 512];
}

// ======================= 128x64 engine (pv only) =======================
__device__ __forceinline__ void mma_compute(
    const float (*Ab)[APAD], const float (*Bb)[BPAD],
    int m_base, int n_base, int gid, int tig, float (&acc)[2][4][4])
{
    #pragma unroll
    for (int ks = 0; ks < 16; ks += 8) {
        uint32_t a[2][4];
        #pragma unroll
        for (int mf = 0; mf < 2; mf++) {
            int m0 = m_base + mf * 16 + gid;
            a[mf][0] = __float_as_uint(Ab[ks + tig][m0]);
            a[mf][1] = __float_as_uint(Ab[ks + tig][m0 + 8]);
            a[mf][2] = __float_as_uint(Ab[ks + tig + 4][m0]);
            a[mf][3] = __float_as_uint(Ab[ks + tig + 4][m0 + 8]);
        }
        #pragma unroll
        for (int nf = 0; nf < 4; nf++) {
            int n0 = n_base + nf * 8 + gid;
            uint32_t b0 = __float_as_uint(Bb[ks + tig][n0]);
            uint32_t b1 = __float_as_uint(Bb[ks + tig + 4][n0]);
            mma_tf32(acc[0][nf], a[0], b0, b1);
            mma_tf32(acc[1][nf], a[1], b0, b1);
        }
    }
}

__device__ __forceinline__ void mma_tile(
    const float* __restrict__ A, int lda,
    const float* __restrict__ B, int ldb,
    int kLen,
    float (*As)[16][APAD], float (*Bs)[16][BPAD],
    float (&acc)[2][4][4])
{
    int tid = threadIdx.x;
    int ar = tid >> 1, ac = (tid & 1) * 8;
    int br = tid >> 4, bc = (tid & 15) * 4;
    int lane = tid & 31, wid = tid >> 5;
    int gid = lane >> 2, tig = lane & 3;
    int m_base = (wid & 3) * 32, n_base = (wid >> 2) * 32;

    const float* Ap = A + (size_t)ar * lda + ac;
    const float* Bp = B + (size_t)br * ldb + bc;

    {
        float4 av0 = *(const float4*)(Ap);
        float4 av1 = *(const float4*)(Ap + 4);
        float4 bv  = *(const float4*)(Bp);
        As[0][ac + 0][ar] = to_tf32(av0.x); As[0][ac + 1][ar] = to_tf32(av0.y);
        As[0][ac + 2][ar] = to_tf32(av0.z); As[0][ac + 3][ar] = to_tf32(av0.w);
        As[0][ac + 4][ar] = to_tf32(av1.x); As[0][ac + 5][ar] = to_tf32(av1.y);
        As[0][ac + 6][ar] = to_tf32(av1.z); As[0][ac + 7][ar] = to_tf32(av1.w);
        float4 bt = make_float4(to_tf32(bv.x), to_tf32(bv.y), to_tf32(bv.z), to_tf32(bv.w));
        *(float4*)&Bs[0][br][bc] = bt;
    }
    __syncthreads();

    int kc = kLen >> 4;
    for (int c = 1; c < kc; c++) {
        const float* Ac = Ap + c * 16;
        float4 av0 = *(const float4*)(Ac);
        float4 av1 = *(const float4*)(Ac + 4);
        float4 bv  = *(const float4*)(Bp + (size_t)(c * 16) * ldb);
        int pb = (c - 1) & 1, nb = c & 1;
        mma_compute(As[pb], Bs[pb], m_base, n_base, gid, tig, acc);
        As[nb][ac + 0][ar] = to_tf32(av0.x); As[nb][ac + 1][ar] = to_tf32(av0.y);
        As[nb][ac + 2][ar] = to_tf32(av0.z); As[nb][ac + 3][ar] = to_tf32(av0.w);
        As[nb][ac + 4][ar] = to_tf32(av1.x); As[nb][ac + 5][ar] = to_tf32(av1.y);
        As[nb][ac + 6][ar] = to_tf32(av1.z); As[nb][ac + 7][ar] = to_tf32(av1.w);
        float4 bt = make_float4(to_tf32(bv.x), to_tf32(bv.y), to_tf32(bv.z), to_tf32(bv.w));
        *(float4*)&Bs[nb][br][bc] = bt;
        __syncthreads();
    }
    int lb = (kc - 1) & 1;
    mma_compute(As[lb], Bs[lb], m_base, n_base, gid, tig, acc);
}

// ======================= 128x128 engine (qkv / Wo / FF) =======================
// 8 warps as 2(m) x 4(n); warp tile 64x32; mf=4, nf=4.
__device__ __forceinline__ void mma_compute128(
    const float (*Ab)[APAD], const float (*Bb)[BPAD2],
    int m_base, int n_base, int gid, int tig, float (&acc)[4][4][4])
{
    #pragma unroll
    for (int ks = 0; ks < 16; ks += 8) {
        uint32_t a[4][4];
        #pragma unroll
        for (int mf = 0; mf < 4; mf++) {
            int m0 = m_base + mf * 16 + gid;
            a[mf][0] = __float_as_uint(Ab[ks + tig][m0]);
            a[mf][1] = __float_as_uint(Ab[ks + tig][m0 + 8]);
            a[mf][2] = __float_as_uint(Ab[ks + tig + 4][m0]);
            a[mf][3] = __float_as_uint(Ab[ks + tig + 4][m0 + 8]);
        }
        #pragma unroll
        for (int nf = 0; nf < 4; nf++) {
            int n0 = n_base + nf * 8 + gid;
            uint32_t b0 = __float_as_uint(Bb[ks + tig][n0]);
            uint32_t b1 = __float_as_uint(Bb[ks + tig + 4][n0]);
            #pragma unroll
            for (int mf = 0; mf < 4; mf++)
                mma_tf32(acc[mf][nf], a[mf], b0, b1);
        }
    }
}

__device__ __forceinline__ void mma_tile128(
    const float* __restrict__ A, int lda,
    const float* __restrict__ B, int ldb,
    int kLen,
    float (*As)[16][APAD], float (*Bs)[16][BPAD2],
    float (&acc)[4][4][4])
{
    int tid = threadIdx.x;
    int ar = tid >> 1, ac = (tid & 1) * 8;
    int br = tid >> 4, bc = (tid & 15) * 4;   // B: row br, cols bc and bc+64
    int lane = tid & 31, wid = tid >> 5;
    int gid = lane >> 2, tig = lane & 3;
    int m_base = (wid & 1) * 64, n_base = (wid >> 1) * 32;

    const float* Ap = A + (size_t)ar * lda + ac;
    const float* Bp = B + (size_t)br * ldb + bc;

    {
        float4 av0 = *(const float4*)(Ap);
        float4 av1 = *(const float4*)(Ap + 4);
        float4 bv0 = *(const float4*)(Bp);
        float4 bv1 = *(const float4*)(Bp + 64);
        As[0][ac + 0][ar] = to_tf32(av0.x); As[0][ac + 1][ar] = to_tf32(av0.y);
        As[0][ac + 2][ar] = to_tf32(av0.z); As[0][ac + 3][ar] = to_tf32(av0.w);
        As[0][ac + 4][ar] = to_tf32(av1.x); As[0][ac + 5][ar] = to_tf32(av1.y);
        As[0][ac + 6][ar] = to_tf32(av1.z); As[0][ac + 7][ar] = to_tf32(av1.w);
        float4 bt0 = make_float4(to_tf32(bv0.x), to_tf32(bv0.y), to_tf32(bv0.z), to_tf32(bv0.w));
        float4 bt1 = make_float4(to_tf32(bv1.x), to_tf32(bv1.y), to_tf32(bv1.z), to_tf32(bv1.w));
        *(float4*)&Bs[0][br][bc]      = bt0;
        *(float4*)&Bs[0][br][bc + 64] = bt1;
    }
    __syncthreads();

    int kc = kLen >> 4;
    for (int c = 1; c < kc; c++) {
        const float* Ac = Ap + c * 16;
        const float* Bc = Bp + (size_t)(c * 16) * ldb;
        float4 av0 = *(const float4*)(Ac);
        float4 av1 = *(const float4*)(Ac + 4);
        float4 bv0 = *(const float4*)(Bc);
        float4 bv1 = *(const float4*)(Bc + 64);
        int pb = (c - 1) & 1, nb = c & 1;
        mma_compute128(As[pb], Bs[pb], m_base, n_base, gid, tig, acc);
        As[nb][ac + 0][ar] = to_tf32(av0.x); As[nb][ac + 1][ar] = to_tf32(av0.y);
        As[nb][ac + 2][ar] = to_tf32(av0.z); As[nb][ac + 3][ar] = to_tf32(av0.w);
        As[nb][ac + 4][ar] = to_tf32(av1.x); As[nb][ac + 5][ar] = to_tf32(av1.y);
        As[nb][ac + 6][ar] = to_tf32(av1.z); As[nb][ac + 7][ar] = to_tf32(av1.w);
        float4 bt0 = make_float4(to_tf32(bv0.x), to_tf32(bv0.y), to_tf32(bv0.z), to_tf32(bv0.w));
        float4 bt1 = make_float4(to_tf32(bv1.x), to_tf32(bv1.y), to_tf32(bv1.z), to_tf32(bv1.w));
        *(float4*)&Bs[nb][br][bc]      = bt0;
        *(float4*)&Bs[nb][br][bc + 64] = bt1;
        __syncthreads();
    }
    int lb = (kc - 1) & 1;
    mma_compute128(As[lb], Bs[lb], m_base, n_base, gid, tig, acc);
}

// ---------------- fused QKV: grid (18,16); blockIdx.x/6 selects matrix ----------------
__global__ void __launch_bounds__(256, 2) qkv_kernel(
    const float* __restrict__ x,
    const float* __restrict__ Wq, const float* __restrict__ Wk, const float* __restrict__ Wv,
    const float* __restrict__ bq, const float* __restrict__ bk, const float* __restrict__ bv,
    float* __restrict__ q, float* __restrict__ k, float* __restrict__ v)
{
    __shared__ float As[2][16][APAD];
    __shared__ float Bs[2][16][BPAD2];
    int sel = blockIdx.x / 6;
    int bn  = (blockIdx.x % 6) * 128;
    int bm  = blockIdx.y * 128;
    const float* B    = sel == 0 ? Wq : (sel == 1 ? Wk : Wv);
    const float* bias = sel == 0 ? bq : (sel == 1 ? bk : bv);
    float* C          = sel == 0 ? q  : (sel == 1 ? k  : v);
    float acc[4][4][4] = {};
    mma_tile128(x + (size_t)bm * HID, HID, B + bn, HID, HID, As, Bs, acc);
    int tid = threadIdx.x, lane = tid & 31, wid = tid >> 5;
    int gid = lane >> 2, tig = lane & 3;
    int m_base = (wid & 1) * 64, n_base = (wid >> 1) * 32;
    #pragma unroll
    for (int mf = 0; mf < 4; mf++) {
        int r0 = bm + m_base + mf * 16 + gid;
        #pragma unroll
        for (int nf = 0; nf < 4; nf++) {
            int col = bn + n_base + nf * 8 + tig * 2;
            float2 bi = *(const float2*)(bias + col);
            *(float2*)(C + (size_t)r0 * HID + col) =
                make_float2(acc[mf][nf][0] + bi.x, acc[mf][nf][1] + bi.y);
            *(float2*)(C + (size_t)(r0 + 8) * HID + col) =
                make_float2(acc[mf][nf][2] + bi.x, acc[mf][nf][3] + bi.y);
        }
    }
}

// ---------------- generic gemm: grid (N/128, M/128); mode 0=+bias 2=gelu(+bias) ----------------
__global__ void __launch_bounds__(256, 2) gemm_kernel(
    const float* __restrict__ A, int K,
    const float* __restrict__ B, int N,
    const float* __restrict__ bias,
    float* __restrict__ C, int mode)
{
    __shared__ float As[2][16][APAD];
    __shared__ float Bs[2][16][BPAD2];
    int bm = blockIdx.y * 128, bn = blockIdx.x * 128;
    float acc[4][4][4] = {};
    mma_tile128(A + (size_t)bm * K, K, B + bn, N, K, As, Bs, acc);
    int tid = threadIdx.x, lane = tid & 31, wid = tid >> 5;
    int gid = lane >> 2, tig = lane & 3;
    int m_base = (wid & 1) * 64, n_base = (wid >> 1) * 32;
    #pragma unroll
    for (int mf = 0; mf < 4; mf++) {
        int r0 = bm + m_base + mf * 16 + gid;
        #pragma unroll
        for (int nf = 0; nf < 4; nf++) {
            int col = bn + n_base + nf * 8 + tig * 2;
            float2 bi = *(const float2*)(bias + col);
            float o0 = acc[mf][nf][0] + bi.x, o1 = acc[mf][nf][1] + bi.y;
            float o2 = acc[mf][nf][2] + bi.x, o3 = acc[mf][nf][3] + bi.y;
            if (mode == 2) { o0 = gelu1(o0); o1 = gelu1(o1); o2 = gelu1(o2); o3 = gelu1(o3); }
            *(float2*)(C + (size_t)r0 * N + col)       = make_float2(o0, o1);
            *(float2*)(C + (size_t)(r0 + 8) * N + col) = make_float2(o2, o3);
        }
    }
}

// ---------------- split-K=2 gemm: grid (N/128, M/128, 2) -> raw partials ----------------
__global__ void __launch_bounds__(256, 2) gemm_split_kernel(
    const float* __restrict__ A, int K,
    const float* __restrict__ B, int N,
    float* __restrict__ P1, float* __restrict__ P2)
{
    __shared__ float As[2][16][APAD];
    __shared__ float Bs[2][16][BPAD2];
    int bm = blockIdx.y * 128, bn = blockIdx.x * 128;
    int half = K >> 1, z = blockIdx.z;
    float acc[4][4][4] = {};
    mma_tile128(A + (size_t)bm * K + z * half, K,
                B + (size_t)(z * half) * N + bn, N, half, As, Bs, acc);
    float* C = z ? P2 : P1;
    int tid = threadIdx.x, lane = tid & 31, wid = tid >> 5;
    int gid = lane >> 2, tig = lane & 3;
    int m_base = (wid & 1) * 64, n_base = (wid >> 1) * 32;
    #pragma unroll
    for (int mf = 0; mf < 4; mf++) {
        int r0 = bm + m_base + mf * 16 + gid;
        #pragma unroll
        for (int nf = 0; nf < 4; nf++) {
            int col = bn + n_base + nf * 8 + tig * 2;
            *(float2*)(C + (size_t)r0 * N + col)       = make_float2(acc[mf][nf][0], acc[mf][nf][1]);
            *(float2*)(C + (size_t)(r0 + 8) * N + col) = make_float2(acc[mf][nf][2], acc[mf][nf][3]);
        }
    }
}

// ---------------- epilogue: out = p1 + p2 + bias + res ----------------
__global__ void epi_kernel(const float* __restrict__ p1, const float* __restrict__ p2,
                           const float* __restrict__ bias, const float* __restrict__ res,
                           float* __restrict__ out)
{
    int idx = (blockIdx.x * 256 + threadIdx.x) * 4;
    int col = idx % HID;
    float4 a  = *(const float4*)(p1 + idx);
    float4 b  = *(const float4*)(p2 + idx);
    float4 r  = *(const float4*)(res + idx);
    float4 bi = *(const float4*)(bias + col);
    float4 o = make_float4(a.x + b.x + r.x + bi.x, a.y + b.y + r.y + bi.y,
                           a.z + b.z + r.z + bi.z, a.w + b.w + r.w + bi.w);
    *(float4*)(out + idx) = o;
}

// ---------------- L1 distance (f32x2 packed): tile 128(q) x 64(k), 8x4 microtile ----------------
__global__ void __launch_bounds__(256) dist_kernel(
    const float* __restrict__ Q, const float* __restrict__ Km,
    const float* __restrict__ lamp, float* __restrict__ attn)
{
    __shared__ unsigned long long Qs[32][128];   // [d-pair][q-row]
    __shared__ unsigned long long Ks[32][64];    // negated K
    int bh = blockIdx.z, b = bh / NHEAD, h = bh - b * NHEAD;
    int qbase = blockIdx.y * 128, kbase = blockIdx.x * 64;
    const float* Qb = Q  + (size_t)b * SEQ * HID + h * HDIM + (size_t)qbase * HID;
    const float* Kb = Km + (size_t)b * SEQ * HID + h * HDIM + (size_t)kbase * HID;
    int tid = threadIdx.x;

    union F2U { float2 f; unsigned long long u; };
    {   // Q: 128 rows, each thread loads 32 dims of one row
        int row = tid >> 1, hh = (tid & 1) * 32;
        #pragma unroll
        for (int i = 0; i < 8; i++) {
            float4 qv = *(const float4*)(Qb + (size_t)row * HID + hh + i * 4);
            F2U t;
            t.f = make_float2(qv.x, qv.y); Qs[(hh >> 1) + i * 2][row]     = t.u;
            t.f = make_float2(qv.z, qv.w); Qs[(hh >> 1) + i * 2 + 1][row] = t.u;
        }
    }
    {   // K: 64 rows, each thread loads 16 dims of one row (negated)
        int row = tid >> 2, kq = (tid & 3) * 16;
        #pragma unroll
        for (int i = 0; i < 4; i++) {
            float4 kv = *(const float4*)(Kb + (size_t)row * HID + kq + i * 4);
            F2U t;
            t.f = make_float2(-kv.x, -kv.y); Ks[(kq >> 1) + i * 2][row]     = t.u;
            t.f = make_float2(-kv.z, -kv.w); Ks[(kq >> 1) + i * 2 + 1][row] = t.u;
        }
    }
    __syncthreads();

    int tx = tid & 15, ty = tid >> 4;
    int qs = ty * 8, ks = tx * 4;
    unsigned long long acc[8][4] = {};
    const unsigned long long MASK = 0x7FFFFFFF7FFFFFFFull;
    #pragma unroll 4
    for (int d = 0; d < 32; d++) {
        unsigned long long qv[8], kv[4];
        *(ulonglong2*)&qv[0] = *(const ulonglong2*)&Qs[d][qs];
        *(ulonglong2*)&qv[2] = *(const ulonglong2*)&Qs[d][qs + 2];
        *(ulonglong2*)&qv[4] = *(const ulonglong2*)&Qs[d][qs + 4];
        *(ulonglong2*)&qv[6] = *(const ulonglong2*)&Qs[d][qs + 6];
        *(ulonglong2*)&kv[0] = *(const ulonglong2*)&Ks[d][ks];
        *(ulonglong2*)&kv[2] = *(const ulonglong2*)&Ks[d][ks + 2];
        #pragma unroll
        for (int i = 0; i < 8; i++)
            #pragma unroll
            for (int j = 0; j < 4; j++) {
                unsigned long long df = f2add(qv[i], kv[j]) & MASK;
                acc[i][j] = f2add(acc[i][j], df);
            }
    }
    float c = -(*lamp) * 0.125f;   // scale = 1/sqrt(64)
    float* outp = attn + (size_t)bh * SEQ * SEQ + (size_t)(qbase + qs) * SEQ + kbase + ks;
    #pragma unroll
    for (int i = 0; i < 8; i++) {
        float4 o;
        F2U t;
        t.u = acc[i][0]; o.x = c * (t.f.x + t.f.y);
        t.u = acc[i][1]; o.y = c * (t.f.x + t.f.y);
        t.u = acc[i][2]; o.z = c * (t.f.x + t.f.y);
        t.u = acc[i][3]; o.w = c * (t.f.x + t.f.y);
        *(float4*)(outp + (size_t)i * SEQ) = o;
    }
}

// ---------------- row softmax in place (rows of 1024) ----------------
__global__ void softmax_kernel(float* __restrict__ attn) {
    size_t row = blockIdx.x;
    float* p = attn + row * SEQ;
    int t = threadIdx.x;
    float4 v = *(float4*)(p + t * 4);
    __shared__ float sh[8];
    float mx = fmaxf(fmaxf(v.x, v.y), fmaxf(v.z, v.w));
    #pragma unroll
    for (int o = 16; o; o >>= 1) mx = fmaxf(mx, __shfl_xor_sync(0xffffffffu, mx, o));
    if (!(t & 31)) sh[t >> 5] = mx;
    __syncthreads();
    float m = sh[0];
    #pragma unroll
    for (int i = 1; i < 8; i++) m = fmaxf(m, sh[i]);
    __syncthreads();
    float4 e;
    e.x = expf(v.x - m); e.y = expf(v.y - m);
    e.z = expf(v.z - m); e.w = expf(v.w - m);
    float s = e.x + e.y + e.z + e.w;
    #pragma unroll
    for (int o = 16; o; o >>= 1) s += __shfl_xor_sync(0xffffffffu, s, o);
    if (!(t & 31)) sh[t >> 5] = s;
    __syncthreads();
    float tot = 0.f;
    #pragma unroll
    for (int i = 0; i < 8; i++) tot += sh[i];
    float inv = 1.f / tot;
    e.x *= inv; e.y *= inv; e.z *= inv; e.w *= inv;
    *(float4*)(p + t * 4) = e;
}

// ---------------- out = attn @ V per head: grid (8,1,24), 128x64 tf32 engine ----------------
__global__ void __launch_bounds__(256, 2) pv_kernel(
    const float* __restrict__ attn, const float* __restrict__ V, float* __restrict__ O)
{
    __shared__ float As[2][16][APAD];
    __shared__ float Bs[2][16][BPAD];
    int bh = blockIdx.z, b = bh / NHEAD, h = bh - b * NHEAD;
    int bm = blockIdx.x * 128;
    const float* A  = attn + (size_t)bh * SEQ * SEQ + (size_t)bm * SEQ;
    const float* Bv = V + (size_t)b * SEQ * HID + h * HDIM;
    float acc[2][4][4] = {};
    mma_tile(A, SEQ, Bv, HID, SEQ, As, Bs, acc);
    float* Ob = O + (size_t)b * SEQ * HID + h * HDIM + (size_t)bm * HID;
    int tid = threadIdx.x, lane = tid & 31, wid = tid >> 5;
    int gid = lane >> 2, tig = lane & 3;
    int m_base = (wid & 3) * 32, n_base = (wid >> 2) * 32;
    #pragma unroll
    for (int mf = 0; mf < 2; mf++) {
        int r0 = m_base + mf * 16 + gid;
        #pragma unroll
        for (int nf = 0; nf < 4; nf++) {
            int col = n_base + nf * 8 + tig * 2;
            *(float2*)(Ob + (size_t)r0 * HID + col)       = make_float2(acc[mf][nf][0], acc[mf][nf][1]);
            *(float2*)(Ob + (size_t)(r0 + 8) * HID + col) = make_float2(acc[mf][nf][2], acc[mf][nf][3]);
        }
    }
}

// ---------------- launch ----------------
extern "C" void kernel_launch(void* const* d_in, const int* in_sizes, int n_in,
                              void* d_out, int out_size) {
    const float* hidden = (const float*)d_in[0];
    const float* ln1g = (const float*)d_in[1];
    const float* ln1b = (const float*)d_in[2];
    const float* Wq = (const float*)d_in[3];
    const float* bq = (const float*)d_in[4];
    const float* Wk = (const float*)d_in[5];
    const float* bk = (const float*)d_in[6];
    const float* Wv = (const float*)d_in[7];
    const float* bv = (const float*)d_in[8];
    const float* Wo = (const float*)d_in[9];
    const float* bo = (const float*)d_in[10];
    const float* lam = (const float*)d_in[11];
    const float* ln2g = (const float*)d_in[12];
    const float* ln2b = (const float*)d_in[13];
    const float* W1 = (const float*)d_in[14];
    const float* b1 = (const float*)d_in[15];
    const float* W2 = (const float*)d_in[16];
    const float* b2 = (const float*)d_in[17];

    float* out0 = (float*)d_out;
    float* attn = out0 + (size_t)MTOT * HID;  // [B,NH,S,S] follows [B,S,H]

    float *x, *q, *k, *v, *ao, *r1, *y, *ff;
    cudaGetSymbolAddress((void**)&x,  g_x);
    cudaGetSymbolAddress((void**)&q,  g_q);
    cudaGetSymbolAddress((void**)&k,  g_k);
    cudaGetSymbolAddress((void**)&v,  g_v);
    cudaGetSymbolAddress((void**)&ao, g_ao);
    cudaGetSymbolAddress((void**)&r1, g_r1);
    cudaGetSymbolAddress((void**)&y,  g_y);
    cudaGetSymbolAddress((void**)&ff, g_ff);

    int epiGrid = (MTOT * HID) / (256 * 4);   // 1536

    ln_kernel<<<MTOT, 256>>>(hidden, ln1g, ln1b, x);
    qkv_kernel<<<dim3(18, 16), 256>>>(x, Wq, Wk, Wv, bq, bk, bv, q, k, v);
    dist_kernel<<<dim3(SEQ / 64, SEQ / 128, BHTOT), 256>>>(q, k, lam, attn);
    softmax_kernel<<<BHTOT * SEQ, 256>>>(attn);
    pv_kernel<<<dim3(SEQ / 128, 1, BHTOT), 256>>>(attn, v, ao);
    // Wo with split-K=2: partials in g_x (x free) and g_ff (free until FF1)
    gemm_split_kernel<<<dim3(6, 16, 2), 256>>>(ao, HID, Wo, HID, x, ff);
    epi_kernel<<<epiGrid, 256>>>(x, ff, bo, hidden, r1);
    ln_kernel<<<MTOT, 256>>>(r1, ln2g, ln2b, y);
    gemm_kernel<<<dim3(24, 16), 256>>>(y, HID, W1, FFD, b1, ff, 2);          // gelu (N=3072)
    // FF2 with split-K=2: partials in g_x and g_q (both free now)
    gemm_split_kernel<<<dim3(6, 16, 2), 256>>>(ff, FFD, W2, HID, x, q);
    epi_kernel<<<epiGrid, 256>>>(x, q, b2, r1, out0);
}